// round 11
// baseline (speedup 1.0000x reference)
#include <cuda_runtime.h>
#include <cuda_bf16.h>
#include <cuda_fp16.h>
#include <math.h>
#include <stdint.h>

// Problem constants
#define SS_ 512   // sequence
#define UU_ 128   // users (batch)
#define HH_ 512   // hidden
#define H3_ 1536  // 3*H
#define VV_ 2048  // vocab
#define F_DAY 86400.0f
#define F_LT  0.1f
#define F_LS  1.0f

#define GRU_BLOCKS 128
#define GRU_THREADS 128

typedef unsigned long long u64t;

// ---------------- packed fp32x2 helpers (Blackwell FFMA2) --------------------
__device__ __forceinline__ u64t pk2(float lo, float hi) {
    u64t r; asm("mov.b64 %0, {%1, %2};" : "=l"(r) : "f"(lo), "f"(hi)); return r;
}
__device__ __forceinline__ void ffma2(u64t& d, u64t a, u64t b) {
    asm("fma.rn.f32x2 %0, %1, %2, %0;" : "+l"(d) : "l"(a), "l"(b));
}
__device__ __forceinline__ float2 upk(u64t v) {
    float2 r; asm("mov.b64 {%0, %1}, %2;" : "=f"(r.x), "=f"(r.y) : "l"(v)); return r;
}

// ---------------- fp16 mma.sync helpers (standard PTX, works on sm_103) ------
__device__ __forceinline__ void mma_hf(float* d, const uint32_t* a, uint32_t b0, uint32_t b1) {
    asm volatile(
        "mma.sync.aligned.m16n8k16.row.col.f32.f16.f16.f32 "
        "{%0,%1,%2,%3}, {%4,%5,%6,%7}, {%8,%9}, {%0,%1,%2,%3};"
        : "+f"(d[0]), "+f"(d[1]), "+f"(d[2]), "+f"(d[3])
        : "r"(a[0]), "r"(a[1]), "r"(a[2]), "r"(a[3]), "r"(b0), "r"(b1));
}
// pack float4 -> 4 fp16 (uint2)
__device__ __forceinline__ uint2 cvt4h(float4 v) {
    __half2 p0 = __floats2half2_rn(v.x, v.y);
    __half2 p1 = __floats2half2_rn(v.z, v.w);
    uint2 r;
    r.x = *reinterpret_cast<uint32_t*>(&p0);
    r.y = *reinterpret_cast<uint32_t*>(&p1);
    return r;
}

// ---------------- scratch (device globals; allocation is banned) -------------
__device__ float g_P[(size_t)VV_ * H3_];          // P = emb @ Wih^T + bih  (12.6MB, L2)
__device__ float g_out[(size_t)SS_ * UU_ * HH_];  // [S][U][H]  GRU outputs
__device__ __half g_outw_h[(size_t)SS_ * UU_ * HH_];  // outw (fp16)
__device__ float g_w[(size_t)UU_ * SS_ * SS_];    // [U][S][S]  causal weights
__device__ float g_sumw[UU_ * SS_];               // [U][S]
__device__ float g_WihT[HH_ * H3_];               // [K=H][N=3H] for P gemm
__device__ float g_WhhT[HH_ * H3_];               // [K=H][N=3H] for GRU
__device__ __half g_fcw_h[(size_t)VV_ * HH_];     // fc_w fp16 hi
__device__ __half g_fcw_l[(size_t)VV_ * HH_];     // fc_w fp16 lo (residual)
__device__ float g_tT[UU_ * SS_];                 // t transposed [U][S]
__device__ float g_sx[UU_ * SS_];
__device__ float g_sy[UU_ * SS_];
__device__ float g_ghp[2 * UU_ * H3_];            // split-K partials of gh
__device__ unsigned g_cnt;                        // global barrier counter

// ---------------- prep: transposes + fcw fp16 split + t/s + barrier reset ----
__global__ void prep_kernel(const float* __restrict__ Wih,
                            const float* __restrict__ Whh,
                            const float* __restrict__ fcw,
                            const float* __restrict__ t,
                            const float* __restrict__ s)
{
    int idx = blockIdx.x * blockDim.x + threadIdx.x;
    if (idx == 0) g_cnt = 0;                      // reset software barrier each replay
    if (idx < HH_ * H3_) {
        int k = idx / H3_, n = idx % H3_;
        g_WihT[idx] = Wih[(size_t)n * HH_ + k];
        g_WhhT[idx] = Whh[(size_t)n * HH_ + k];
    }
    if (idx < VV_ * HH_) {
        float f = fcw[idx];
        __half h = __float2half_rn(f);
        g_fcw_h[idx] = h;
        g_fcw_l[idx] = __float2half_rn(f - __half2float(h));
    }
    if (idx < UU_ * SS_) {
        int u = idx / SS_, i = idx % SS_;
        g_tT[idx] = t[(size_t)i * UU_ + u];
        g_sx[idx] = s[((size_t)i * UU_ + u) * 2 + 0];
        g_sy[idx] = s[((size_t)i * UU_ + u) * 2 + 1];
    }
}

// ---------------- P GEMM: P = emb @ Wih^T + bih (FFMA2 128x128x16) -----------
__global__ __launch_bounds__(256, 2)
void pgemm(const float* __restrict__ emb, const float* __restrict__ bih)
{
    const int n0 = blockIdx.x * 128;
    const int m0 = blockIdx.y * 128;
    const float* A = emb;     const int lda = HH_;
    const float* B = g_WihT;  const int ldb = H3_;
    float*       C = g_P;     const int ldc = H3_;

    __shared__ float As[2][16][128];
    __shared__ float Bs[2][16][128];

    const int tid = threadIdx.x;
    const int tx4 = (tid & 15) * 4;
    const int ty4 = (tid >> 4) * 4;

    const int ar  = tid >> 1;
    const int akk = (tid & 1) * 8;
    const float* aRow = A + (size_t)(m0 + ar) * lda + akk;
    const int br  = tid >> 4;
    const int bcc = (tid & 15) * 8;
    const float* bPtr = B + (size_t)br * ldb + n0 + bcc;

    u64t acc[4][8];
#pragma unroll
    for (int i = 0; i < 4; i++)
#pragma unroll
        for (int j = 0; j < 8; j++) acc[i][j] = 0ULL;

    float4 pa0 = *(const float4*)(aRow);
    float4 pa1 = *(const float4*)(aRow + 4);
    float4 pb0 = *(const float4*)(bPtr);
    float4 pb1 = *(const float4*)(bPtr + 4);
    As[0][akk + 0][ar] = pa0.x; As[0][akk + 1][ar] = pa0.y;
    As[0][akk + 2][ar] = pa0.z; As[0][akk + 3][ar] = pa0.w;
    As[0][akk + 4][ar] = pa1.x; As[0][akk + 5][ar] = pa1.y;
    As[0][akk + 6][ar] = pa1.z; As[0][akk + 7][ar] = pa1.w;
    *(float4*)&Bs[0][br][bcc]     = pb0;
    *(float4*)&Bs[0][br][bcc + 4] = pb1;
    __syncthreads();

    const int nk = HH_ >> 4;
    int buf = 0;
    for (int kt = 0; kt < nk; kt++) {
        if (kt + 1 < nk) {
            int kn = (kt + 1) << 4;
            pa0 = *(const float4*)(aRow + kn);
            pa1 = *(const float4*)(aRow + kn + 4);
            pb0 = *(const float4*)(bPtr + (size_t)kn * ldb);
            pb1 = *(const float4*)(bPtr + (size_t)kn * ldb + 4);
        }
#pragma unroll
        for (int k = 0; k < 16; k++) {
            float4 a0 = *(const float4*)&As[buf][k][ty4];
            float4 a1 = *(const float4*)&As[buf][k][64 + ty4];
            float4 b0 = *(const float4*)&Bs[buf][k][tx4];
            float4 b1 = *(const float4*)&Bs[buf][k][64 + tx4];
            u64t ap[4];
            ap[0] = pk2(a0.x, a0.y); ap[1] = pk2(a0.z, a0.w);
            ap[2] = pk2(a1.x, a1.y); ap[3] = pk2(a1.z, a1.w);
            u64t bd[8];
            bd[0] = pk2(b0.x, b0.x); bd[1] = pk2(b0.y, b0.y);
            bd[2] = pk2(b0.z, b0.z); bd[3] = pk2(b0.w, b0.w);
            bd[4] = pk2(b1.x, b1.x); bd[5] = pk2(b1.y, b1.y);
            bd[6] = pk2(b1.z, b1.z); bd[7] = pk2(b1.w, b1.w);
#pragma unroll
            for (int i = 0; i < 4; i++)
#pragma unroll
                for (int j = 0; j < 8; j++)
                    ffma2(acc[i][j], ap[i], bd[j]);
        }
        if (kt + 1 < nk) {
            int nb = buf ^ 1;
            As[nb][akk + 0][ar] = pa0.x; As[nb][akk + 1][ar] = pa0.y;
            As[nb][akk + 2][ar] = pa0.z; As[nb][akk + 3][ar] = pa0.w;
            As[nb][akk + 4][ar] = pa1.x; As[nb][akk + 5][ar] = pa1.y;
            As[nb][akk + 6][ar] = pa1.z; As[nb][akk + 7][ar] = pa1.w;
            *(float4*)&Bs[nb][br][bcc]     = pb0;
            *(float4*)&Bs[nb][br][bcc + 4] = pb1;
            __syncthreads();
            buf = nb;
        }
    }

    float bv[8];
#pragma unroll
    for (int j = 0; j < 8; j++)
        bv[j] = bih[n0 + ((j < 4) ? (tx4 + j) : (64 + tx4 + j - 4))];
#pragma unroll
    for (int mp = 0; mp < 4; mp++) {
        int r = m0 + ((mp >= 2) ? 64 : 0) + ty4 + (mp & 1) * 2;
        float2 v[8];
#pragma unroll
        for (int j = 0; j < 8; j++) v[j] = upk(acc[mp][j]);
        float4 lo0 = make_float4(v[0].x + bv[0], v[1].x + bv[1], v[2].x + bv[2], v[3].x + bv[3]);
        float4 lo1 = make_float4(v[4].x + bv[4], v[5].x + bv[5], v[6].x + bv[6], v[7].x + bv[7]);
        float4 hi0 = make_float4(v[0].y + bv[0], v[1].y + bv[1], v[2].y + bv[2], v[3].y + bv[3]);
        float4 hi1 = make_float4(v[4].y + bv[4], v[5].y + bv[5], v[6].y + bv[6], v[7].y + bv[7]);
        float* c0 = C + (size_t)r * ldc + n0;
        float* c1 = C + (size_t)(r + 1) * ldc + n0;
        *(float4*)&c0[tx4]      = lo0;
        *(float4*)&c0[64 + tx4] = lo1;
        *(float4*)&c1[tx4]      = hi0;
        *(float4*)&c1[64 + tx4] = hi1;
    }
}

// ---------------- fc GEMM: fp16 2-pass mma.sync ------------------------------
// y[m][n] = sum_k outw[m][k]*fcw[n][k] + fcb[n];  A(fp16) * (Bh + Bl)
#define TSTR 40   // smem row stride in fp16 (conflict-free frag loads)

__global__ __launch_bounds__(256, 2)
void tgemm_fc(const float* __restrict__ bias, float* __restrict__ Cout)
{
    __shared__ uint16_t sA [128 * TSTR];
    __shared__ uint16_t sBh[128 * TSTR];
    __shared__ uint16_t sBl[128 * TSTR];

    const int tid = threadIdx.x;
    const int wid = tid >> 5, lid = tid & 31;
    const int g   = lid >> 2, tig = lid & 3;
    const int wm  = wid & 1;
    const int wn  = wid >> 1;
    const int n0  = blockIdx.x * 128;
    const int m0  = blockIdx.y * 128;

    // fill mapping: thread covers row fr, k-half kh (16 fp16 = 2x uint4)
    const int fr = tid >> 1;
    const int kh = (tid & 1) * 16;
    const uint16_t* aS  = (const uint16_t*)g_outw_h + (size_t)(m0 + fr) * HH_ + kh;
    const uint16_t* bhS = (const uint16_t*)g_fcw_h  + (size_t)(n0 + fr) * HH_ + kh;
    const uint16_t* blS = (const uint16_t*)g_fcw_l  + (size_t)(n0 + fr) * HH_ + kh;
    uint4* aD  = (uint4*)&sA [fr * TSTR + kh];
    uint4* bhD = (uint4*)&sBh[fr * TSTR + kh];
    uint4* blD = (uint4*)&sBl[fr * TSTR + kh];

    float acc[4][4][4];
#pragma unroll
    for (int i = 0; i < 4; i++)
#pragma unroll
        for (int j = 0; j < 4; j++)
#pragma unroll
            for (int q = 0; q < 4; q++) acc[i][j][q] = 0.f;

    for (int kb = 0; kb < HH_; kb += 32) {
        __syncthreads();
        {
            const uint4* p;
            p = (const uint4*)(aS  + kb); aD[0]  = p[0]; aD[1]  = p[1];
            p = (const uint4*)(bhS + kb); bhD[0] = p[0]; bhD[1] = p[1];
            p = (const uint4*)(blS + kb); blD[0] = p[0]; blD[1] = p[1];
        }
        __syncthreads();
#pragma unroll
        for (int k16 = 0; k16 < 32; k16 += 16) {
            uint32_t bh[4][2], bl[4][2];
#pragma unroll
            for (int nf = 0; nf < 4; nf++) {
                int nb = (wn * 32 + nf * 8 + g) * TSTR + k16 + 2 * tig;
                bh[nf][0] = *(const uint32_t*)&sBh[nb];
                bh[nf][1] = *(const uint32_t*)&sBh[nb + 8];
                bl[nf][0] = *(const uint32_t*)&sBl[nb];
                bl[nf][1] = *(const uint32_t*)&sBl[nb + 8];
            }
#pragma unroll
            for (int mf = 0; mf < 4; mf++) {
                int ab = (wm * 64 + mf * 16 + g) * TSTR + k16 + 2 * tig;
                uint32_t ah[4];
                ah[0] = *(const uint32_t*)&sA[ab];
                ah[1] = *(const uint32_t*)&sA[ab + 8 * TSTR];
                ah[2] = *(const uint32_t*)&sA[ab + 8];
                ah[3] = *(const uint32_t*)&sA[ab + 8 * TSTR + 8];
#pragma unroll
                for (int nf = 0; nf < 4; nf++) {
                    mma_hf(acc[mf][nf], ah, bh[nf][0], bh[nf][1]);   // A*Bh
                    mma_hf(acc[mf][nf], ah, bl[nf][0], bl[nf][1]);   // A*Bl
                }
            }
        }
    }

#pragma unroll
    for (int nf = 0; nf < 4; nf++) {
        int col = n0 + wn * 32 + nf * 8 + 2 * tig;
        float2 bb = *(const float2*)&bias[col];
#pragma unroll
        for (int mf = 0; mf < 4; mf++) {
            int row = m0 + wm * 64 + mf * 16 + g;
            float2 v0 = make_float2(acc[mf][nf][0] + bb.x, acc[mf][nf][1] + bb.y);
            float2 v1 = make_float2(acc[mf][nf][2] + bb.x, acc[mf][nf][3] + bb.y);
            *(float2*)&Cout[(size_t)row * VV_ + col]       = v0;
            *(float2*)&Cout[(size_t)(row + 8) * VV_ + col] = v1;
        }
    }
}

// ---------------- attention GEMM (FFMA2) -> fp16 outw ------------------------
__global__ __launch_bounds__(256, 2)
void attn_gemm()
{
    const int n0 = blockIdx.x * 128;
    const int m0 = blockIdx.y * 128;
    const int u  = blockIdx.z;
    const float* A = g_w   + (size_t)u * SS_ * SS_;
    const float* B = g_out + (size_t)u * HH_;
    __half* Ch = g_outw_h + (size_t)u * HH_;
    const int lda = SS_, ldb = UU_ * HH_, ldc = UU_ * HH_;
    const int kmax = (SS_ < m0 + 128) ? SS_ : (m0 + 128);

    __shared__ float As[2][16][128];
    __shared__ float Bs[2][16][128];

    const int tid = threadIdx.x;
    const int tx4 = (tid & 15) * 4;
    const int ty4 = (tid >> 4) * 4;

    const int ar  = tid >> 1;
    const int akk = (tid & 1) * 8;
    const float* aRow = A + (size_t)(m0 + ar) * lda + akk;
    const int br  = tid >> 4;
    const int bcc = (tid & 15) * 8;
    const float* bPtr = B + (size_t)br * ldb + n0 + bcc;

    u64t acc[4][8];
#pragma unroll
    for (int i = 0; i < 4; i++)
#pragma unroll
        for (int j = 0; j < 8; j++) acc[i][j] = 0ULL;

    float4 pa0 = *(const float4*)(aRow);
    float4 pa1 = *(const float4*)(aRow + 4);
    float4 pb0 = *(const float4*)(bPtr);
    float4 pb1 = *(const float4*)(bPtr + 4);
    As[0][akk + 0][ar] = pa0.x; As[0][akk + 1][ar] = pa0.y;
    As[0][akk + 2][ar] = pa0.z; As[0][akk + 3][ar] = pa0.w;
    As[0][akk + 4][ar] = pa1.x; As[0][akk + 5][ar] = pa1.y;
    As[0][akk + 6][ar] = pa1.z; As[0][akk + 7][ar] = pa1.w;
    *(float4*)&Bs[0][br][bcc]     = pb0;
    *(float4*)&Bs[0][br][bcc + 4] = pb1;
    __syncthreads();

    const int nk = kmax >> 4;
    int buf = 0;
    for (int kt = 0; kt < nk; kt++) {
        if (kt + 1 < nk) {
            int kn = (kt + 1) << 4;
            pa0 = *(const float4*)(aRow + kn);
            pa1 = *(const float4*)(aRow + kn + 4);
            pb0 = *(const float4*)(bPtr + (size_t)kn * ldb);
            pb1 = *(const float4*)(bPtr + (size_t)kn * ldb + 4);
        }
#pragma unroll
        for (int k = 0; k < 16; k++) {
            float4 a0 = *(const float4*)&As[buf][k][ty4];
            float4 a1 = *(const float4*)&As[buf][k][64 + ty4];
            float4 b0 = *(const float4*)&Bs[buf][k][tx4];
            float4 b1 = *(const float4*)&Bs[buf][k][64 + tx4];
            u64t ap[4];
            ap[0] = pk2(a0.x, a0.y); ap[1] = pk2(a0.z, a0.w);
            ap[2] = pk2(a1.x, a1.y); ap[3] = pk2(a1.z, a1.w);
            u64t bd[8];
            bd[0] = pk2(b0.x, b0.x); bd[1] = pk2(b0.y, b0.y);
            bd[2] = pk2(b0.z, b0.z); bd[3] = pk2(b0.w, b0.w);
            bd[4] = pk2(b1.x, b1.x); bd[5] = pk2(b1.y, b1.y);
            bd[6] = pk2(b1.z, b1.z); bd[7] = pk2(b1.w, b1.w);
#pragma unroll
            for (int i = 0; i < 4; i++)
#pragma unroll
                for (int j = 0; j < 8; j++)
                    ffma2(acc[i][j], ap[i], bd[j]);
        }
        if (kt + 1 < nk) {
            int nb = buf ^ 1;
            As[nb][akk + 0][ar] = pa0.x; As[nb][akk + 1][ar] = pa0.y;
            As[nb][akk + 2][ar] = pa0.z; As[nb][akk + 3][ar] = pa0.w;
            As[nb][akk + 4][ar] = pa1.x; As[nb][akk + 5][ar] = pa1.y;
            As[nb][akk + 6][ar] = pa1.z; As[nb][akk + 7][ar] = pa1.w;
            *(float4*)&Bs[nb][br][bcc]     = pb0;
            *(float4*)&Bs[nb][br][bcc + 4] = pb1;
            __syncthreads();
            buf = nb;
        }
    }

#pragma unroll
    for (int mp = 0; mp < 4; mp++) {
        int r = m0 + ((mp >= 2) ? 64 : 0) + ty4 + (mp & 1) * 2;
        float2 v[8];
#pragma unroll
        for (int j = 0; j < 8; j++) v[j] = upk(acc[mp][j]);
        float s0 = 1.f / g_sumw[u * SS_ + r];
        float s1 = 1.f / g_sumw[u * SS_ + r + 1];
        float4 lo0 = make_float4(v[0].x * s0, v[1].x * s0, v[2].x * s0, v[3].x * s0);
        float4 lo1 = make_float4(v[4].x * s0, v[5].x * s0, v[6].x * s0, v[7].x * s0);
        float4 hi0 = make_float4(v[0].y * s1, v[1].y * s1, v[2].y * s1, v[3].y * s1);
        float4 hi1 = make_float4(v[4].y * s1, v[5].y * s1, v[6].y * s1, v[7].y * s1);
        size_t b0 = (size_t)r * ldc, b1 = (size_t)(r + 1) * ldc;
        *(uint2*)&Ch[b0 + n0 + tx4]      = cvt4h(lo0);
        *(uint2*)&Ch[b0 + n0 + 64 + tx4] = cvt4h(lo1);
        *(uint2*)&Ch[b1 + n0 + tx4]      = cvt4h(hi0);
        *(uint2*)&Ch[b1 + n0 + 64 + tx4] = cvt4h(hi1);
    }
}

// ---------------- persistent GRU: all 512 steps in ONE kernel ----------------
// 128 blocks x 128 threads; per-thread tile 4u x 6n (FMA-bound inner loop)
__device__ __forceinline__ void grid_barrier(unsigned& target)
{
    __syncthreads();
    if (threadIdx.x == 0) {
        __threadfence();
        atomicAdd(&g_cnt, 1u);
        target += GRU_BLOCKS;
        while (*(volatile unsigned*)&g_cnt < target) { }
        __threadfence();
    }
    __syncthreads();
}

#define ASH_STRIDE 532

__global__ __launch_bounds__(GRU_THREADS)
void gru_persistent(const float* __restrict__ h0,
                    const float* __restrict__ bhh,
                    const int* __restrict__ x)
{
    extern __shared__ float dsm[];
    float* Wsh = dsm;                         // [256][96]
    float* Ash = dsm + 256 * 96;              // [32][ASH_STRIDE] dup pairs

    const int bz = blockIdx.x;
    const int kc = bz & 1;
    const int u0 = ((bz >> 1) & 3) * 32;
    const int n0 = (bz >> 3) * 96;
    const int kbase = kc * 256;

    const int tid = threadIdx.x;
    const int ty = tid >> 4;                  // 8 groups of 4 u
    const int tx = tid & 15;                  // 16 groups of 6 n

    for (int fi = tid; fi < 256 * 24; fi += GRU_THREADS) {
        int k = fi / 24, c = fi % 24;
        *(float4*)&Wsh[k * 96 + c * 4] =
            *(const float4*)&g_WhhT[(size_t)(kbase + k) * H3_ + n0 + c * 4];
    }

    const int fu = tid >> 2;                  // fill: u row 0..31
    const int fj = (tid & 3) * 4;             // fill: k offset within 16-chunk

    unsigned target = 0;

    for (int st = 0; st < SS_; st++) {
        const float* hp = (st == 0) ? h0 : (g_out + (size_t)(st - 1) * UU_ * HH_);

        // stage h slice as duplicated pairs: Ash[u][2k],[2k+1] = hp[u0+u][kbase+k]
        {
            const float* hrow = hp + (size_t)(u0 + fu) * HH_ + kbase;
            float* drow = &Ash[fu * ASH_STRIDE];
#pragma unroll
            for (int i = 0; i < 16; i++) {
                int kb = fj + 16 * i;
                float4 v = *(const float4*)&hrow[kb];
                float* d = &drow[2 * kb];
                *(float2*)&d[0] = make_float2(v.x, v.x);
                *(float2*)&d[2] = make_float2(v.y, v.y);
                *(float2*)&d[4] = make_float2(v.z, v.z);
                *(float2*)&d[6] = make_float2(v.w, v.w);
            }
        }
        __syncthreads();

        // ---- phase A: per-thread 4u x 6n FFMA2 over 256 k
        u64t acc[4][3];
#pragma unroll
        for (int i = 0; i < 4; i++) { acc[i][0] = acc[i][1] = acc[i][2] = 0ULL; }
        const float* ar0 = &Ash[(ty * 4 + 0) * ASH_STRIDE];
        const float* ar1 = &Ash[(ty * 4 + 1) * ASH_STRIDE];
        const float* ar2 = &Ash[(ty * 4 + 2) * ASH_STRIDE];
        const float* ar3 = &Ash[(ty * 4 + 3) * ASH_STRIDE];
        const float* bcol = &Wsh[tx * 6];
#pragma unroll 4
        for (int k = 0; k < 256; k++) {
            u64t a0 = *(const u64t*)&ar0[2 * k];
            u64t a1 = *(const u64t*)&ar1[2 * k];
            u64t a2 = *(const u64t*)&ar2[2 * k];
            u64t a3 = *(const u64t*)&ar3[2 * k];
            const float* bk = bcol + k * 96;
            u64t b0 = *(const u64t*)&bk[0];
            u64t b1 = *(const u64t*)&bk[2];
            u64t b2 = *(const u64t*)&bk[4];
            ffma2(acc[0][0], a0, b0); ffma2(acc[0][1], a0, b1); ffma2(acc[0][2], a0, b2);
            ffma2(acc[1][0], a1, b0); ffma2(acc[1][1], a1, b1); ffma2(acc[1][2], a1, b2);
            ffma2(acc[2][0], a2, b0); ffma2(acc[2][1], a2, b1); ffma2(acc[2][2], a2, b2);
            ffma2(acc[3][0], a3, b0); ffma2(acc[3][1], a3, b1); ffma2(acc[3][2], a3, b2);
        }
#pragma unroll
        for (int uu = 0; uu < 4; uu++) {
            float* dst = g_ghp + (size_t)(kc * UU_ + u0 + ty * 4 + uu) * H3_ + n0 + tx * 6;
            *(float2*)&dst[0] = upk(acc[uu][0]);
            *(float2*)&dst[2] = upk(acc[uu][1]);
            *(float2*)&dst[4] = upk(acc[uu][2]);
        }

        grid_barrier(target);

        // ---- phase B: reduce split-K, gates, h update -> g_out[st]
#pragma unroll
        for (int e = 0; e < 4; e++) {
            int idx = e * (GRU_BLOCKS * GRU_THREADS) + bz * GRU_THREADS + tid;
            int u = idx >> 9;
            int j = idx & 511;
            const float* p0 = g_ghp + (size_t)u * H3_;
            const float* p1 = g_ghp + (size_t)(UU_ + u) * H3_;
            float hr = p0[j]        + p1[j]        + bhh[j];
            float hz = p0[512 + j]  + p1[512 + j]  + bhh[512 + j];
            float hn = p0[1024 + j] + p1[1024 + j] + bhh[1024 + j];
            // gi gathered from L2-resident P table
            const float* gi = g_P + (size_t)__ldg(&x[st * UU_ + u]) * H3_;
            float r = 1.f / (1.f + __expf(-(gi[j] + hr)));
            float z = 1.f / (1.f + __expf(-(gi[512 + j] + hz)));
            float a = gi[1024 + j] + r * hn;
            float e2 = __expf(2.f * a);
            float n = 1.f - 2.f / (e2 + 1.f);
            float hprev = hp[(size_t)u * HH_ + j];
            g_out[(size_t)st * UU_ * HH_ + idx] = (1.f - z) * n + z * hprev;
        }

        grid_barrier(target);
    }
}

// ---------------- causal spatiotemporal weight matrix ------------------------
__global__ void wmat_kernel()
{
    const int i = blockIdx.x;
    const int u = blockIdx.y;
    const float ti  = g_tT[u * SS_ + i];
    const float sxi = g_sx[u * SS_ + i];
    const float syi = g_sy[u * SS_ + i];

    float lsum = 0.f;
    for (int j = threadIdx.x; j < SS_; j += 256) {
        float wv = 0.f;
        if (j <= i) {
            float dt = ti - g_tT[u * SS_ + j];
            float dx = sxi - g_sx[u * SS_ + j];
            float dy = syi - g_sy[u * SS_ + j];
            float ds = sqrtf(dx * dx + dy * dy);
            wv = __expf(-dt * (F_LT / F_DAY) - F_LS * ds) + 1e-10f;
        }
        g_w[((size_t)u * SS_ + i) * SS_ + j] = wv;
        lsum += wv;
    }
    __shared__ float red[256];
    red[threadIdx.x] = lsum;
    __syncthreads();
    for (int o = 128; o > 0; o >>= 1) {
        if (threadIdx.x < o) red[threadIdx.x] += red[threadIdx.x + o];
        __syncthreads();
    }
    if (threadIdx.x == 0) g_sumw[u * SS_ + i] = red[0];
}

// copy h_last = out[S-1] to tail of d_out
__global__ void hlast_kernel(float* __restrict__ out)
{
    int i = blockIdx.x * blockDim.x + threadIdx.x;
    if (i < UU_ * HH_)
        out[(size_t)SS_ * UU_ * VV_ + i] = g_out[(size_t)(SS_ - 1) * UU_ * HH_ + i];
}

// ---------------- launcher ---------------------------------------------------
extern "C" void kernel_launch(void* const* d_in, const int* in_sizes, int n_in,
                              void* d_out, int out_size)
{
    const int*   x   = (const int*)d_in[0];
    const float* t   = (const float*)d_in[1];
    const float* s   = (const float*)d_in[2];
    // d_in[3] y_t, d_in[4] y_s, d_in[6] active_user: unused by reference
    const float* h0  = (const float*)d_in[5];
    const float* emb = (const float*)d_in[7];
    const float* Wih = (const float*)d_in[8];
    const float* Whh = (const float*)d_in[9];
    const float* bih = (const float*)d_in[10];
    const float* bhh = (const float*)d_in[11];
    const float* fcw = (const float*)d_in[12];
    const float* fcb = (const float*)d_in[13];
    float* out = (float*)d_out;

    static const int GRU_SMEM = (256 * 96 + 32 * ASH_STRIDE) * 4;
    cudaFuncSetAttribute(gru_persistent,
                         cudaFuncAttributeMaxDynamicSharedMemorySize, GRU_SMEM);

    // 1. transposes + fcw fp16 split + t/s relayout + barrier reset
    prep_kernel<<<(VV_ * HH_ + 255) / 256, 256>>>(Wih, Whh, fcw, t, s);

    // 2. P = emb @ Wih^T + bih  (2048x1536x512 — replaces entire gi GEMM)
    pgemm<<<dim3(H3_ / 128, VV_ / 128), 256>>>(emb, bih);

    // 3. GRU recurrence (gathers gi rows from L2-resident P)
    gru_persistent<<<GRU_BLOCKS, GRU_THREADS, GRU_SMEM>>>(h0, bhh, x);

    // 4. causal spatiotemporal weights + row sums
    wmat_kernel<<<dim3(SS_, UU_), 256>>>();

    // 5. out_w = (w @ out) / sum_w  -> fp16 for fc
    attn_gemm<<<dim3(HH_ / 128, SS_ / 128, UU_), 256>>>();

    // 6. y = out_w @ fc_w^T + fc_b  (fp16 2-pass mma.sync)
    tgemm_fc<<<dim3(VV_ / 128, (SS_ * UU_) / 128), 256>>>(fcb, out);

    // 7. h_last
    hlast_kernel<<<(UU_ * HH_ + 255) / 256, 256>>>(out);
}

// round 12
// speedup vs baseline: 1.1865x; 1.1865x over previous
#include <cuda_runtime.h>
#include <cuda_bf16.h>
#include <cuda_fp16.h>
#include <math.h>
#include <stdint.h>

// Problem constants
#define SS_ 512   // sequence
#define UU_ 128   // users (batch)
#define HH_ 512   // hidden
#define H3_ 1536  // 3*H
#define VV_ 2048  // vocab
#define F_DAY 86400.0f
#define F_LT  0.1f
#define F_LS  1.0f

#define GRU_BLOCKS 128
#define GRU_THREADS 256

typedef unsigned long long u64t;

// ---------------- packed fp32x2 helpers (Blackwell FFMA2) --------------------
__device__ __forceinline__ u64t pk2(float lo, float hi) {
    u64t r; asm("mov.b64 %0, {%1, %2};" : "=l"(r) : "f"(lo), "f"(hi)); return r;
}
__device__ __forceinline__ void ffma2(u64t& d, u64t a, u64t b) {
    asm("fma.rn.f32x2 %0, %1, %2, %0;" : "+l"(d) : "l"(a), "l"(b));
}
__device__ __forceinline__ float2 upk(u64t v) {
    float2 r; asm("mov.b64 {%0, %1}, %2;" : "=f"(r.x), "=f"(r.y) : "l"(v)); return r;
}

// ---------------- fp16 mma.sync helpers (standard PTX, works on sm_103) ------
__device__ __forceinline__ void mma_hf(float* d, const uint32_t* a, uint32_t b0, uint32_t b1) {
    asm volatile(
        "mma.sync.aligned.m16n8k16.row.col.f32.f16.f16.f32 "
        "{%0,%1,%2,%3}, {%4,%5,%6,%7}, {%8,%9}, {%0,%1,%2,%3};"
        : "+f"(d[0]), "+f"(d[1]), "+f"(d[2]), "+f"(d[3])
        : "r"(a[0]), "r"(a[1]), "r"(a[2]), "r"(a[3]), "r"(b0), "r"(b1));
}
// pack float4 -> 4 fp16 (uint2)
__device__ __forceinline__ uint2 cvt4h(float4 v) {
    __half2 p0 = __floats2half2_rn(v.x, v.y);
    __half2 p1 = __floats2half2_rn(v.z, v.w);
    uint2 r;
    r.x = *reinterpret_cast<uint32_t*>(&p0);
    r.y = *reinterpret_cast<uint32_t*>(&p1);
    return r;
}

// ---------------- scratch (device globals; allocation is banned) -------------
__device__ float g_P[(size_t)VV_ * H3_];          // P = emb @ Wih^T + bih  (12.6MB, L2)
__device__ float g_out[(size_t)SS_ * UU_ * HH_];  // [S][U][H]  GRU outputs
__device__ __half g_outw_h[(size_t)SS_ * UU_ * HH_];  // outw (fp16)
__device__ float g_w[(size_t)UU_ * SS_ * SS_];    // [U][S][S]  causal weights
__device__ float g_sumw[UU_ * SS_];               // [U][S]
__device__ float g_WihT[HH_ * H3_];               // [K=H][N=3H] for P gemm
__device__ float g_WhhT[HH_ * H3_];               // [K=H][N=3H] for GRU
__device__ __half g_fcw_h[(size_t)VV_ * HH_];     // fc_w fp16 hi
__device__ __half g_fcw_l[(size_t)VV_ * HH_];     // fc_w fp16 lo (residual)
__device__ float g_tT[UU_ * SS_];                 // t transposed [U][S]
__device__ float g_sx[UU_ * SS_];
__device__ float g_sy[UU_ * SS_];
__device__ float g_ghp[2 * UU_ * H3_];            // split-K partials of gh
__device__ unsigned g_cnt;                        // global barrier counter

// ---------------- prep: transposes + fcw fp16 split + t/s + barrier reset ----
__global__ void prep_kernel(const float* __restrict__ Wih,
                            const float* __restrict__ Whh,
                            const float* __restrict__ fcw,
                            const float* __restrict__ t,
                            const float* __restrict__ s)
{
    int idx = blockIdx.x * blockDim.x + threadIdx.x;
    if (idx == 0) g_cnt = 0;                      // reset software barrier each replay
    if (idx < HH_ * H3_) {
        int k = idx / H3_, n = idx % H3_;
        g_WihT[idx] = Wih[(size_t)n * HH_ + k];
        g_WhhT[idx] = Whh[(size_t)n * HH_ + k];
    }
    if (idx < VV_ * HH_) {
        float f = fcw[idx];
        __half h = __float2half_rn(f);
        g_fcw_h[idx] = h;
        g_fcw_l[idx] = __float2half_rn(f - __half2float(h));
    }
    if (idx < UU_ * SS_) {
        int u = idx / SS_, i = idx % SS_;
        g_tT[idx] = t[(size_t)i * UU_ + u];
        g_sx[idx] = s[((size_t)i * UU_ + u) * 2 + 0];
        g_sy[idx] = s[((size_t)i * UU_ + u) * 2 + 1];
    }
}

// ---------------- P GEMM: P = emb @ Wih^T + bih (FFMA2 128x128x16) -----------
__global__ __launch_bounds__(256, 2)
void pgemm(const float* __restrict__ emb, const float* __restrict__ bih)
{
    const int n0 = blockIdx.x * 128;
    const int m0 = blockIdx.y * 128;
    const float* A = emb;     const int lda = HH_;
    const float* B = g_WihT;  const int ldb = H3_;
    float*       C = g_P;     const int ldc = H3_;

    __shared__ float As[2][16][128];
    __shared__ float Bs[2][16][128];

    const int tid = threadIdx.x;
    const int tx4 = (tid & 15) * 4;
    const int ty4 = (tid >> 4) * 4;

    const int ar  = tid >> 1;
    const int akk = (tid & 1) * 8;
    const float* aRow = A + (size_t)(m0 + ar) * lda + akk;
    const int br  = tid >> 4;
    const int bcc = (tid & 15) * 8;
    const float* bPtr = B + (size_t)br * ldb + n0 + bcc;

    u64t acc[4][8];
#pragma unroll
    for (int i = 0; i < 4; i++)
#pragma unroll
        for (int j = 0; j < 8; j++) acc[i][j] = 0ULL;

    float4 pa0 = *(const float4*)(aRow);
    float4 pa1 = *(const float4*)(aRow + 4);
    float4 pb0 = *(const float4*)(bPtr);
    float4 pb1 = *(const float4*)(bPtr + 4);
    As[0][akk + 0][ar] = pa0.x; As[0][akk + 1][ar] = pa0.y;
    As[0][akk + 2][ar] = pa0.z; As[0][akk + 3][ar] = pa0.w;
    As[0][akk + 4][ar] = pa1.x; As[0][akk + 5][ar] = pa1.y;
    As[0][akk + 6][ar] = pa1.z; As[0][akk + 7][ar] = pa1.w;
    *(float4*)&Bs[0][br][bcc]     = pb0;
    *(float4*)&Bs[0][br][bcc + 4] = pb1;
    __syncthreads();

    const int nk = HH_ >> 4;
    int buf = 0;
    for (int kt = 0; kt < nk; kt++) {
        if (kt + 1 < nk) {
            int kn = (kt + 1) << 4;
            pa0 = *(const float4*)(aRow + kn);
            pa1 = *(const float4*)(aRow + kn + 4);
            pb0 = *(const float4*)(bPtr + (size_t)kn * ldb);
            pb1 = *(const float4*)(bPtr + (size_t)kn * ldb + 4);
        }
#pragma unroll
        for (int k = 0; k < 16; k++) {
            float4 a0 = *(const float4*)&As[buf][k][ty4];
            float4 a1 = *(const float4*)&As[buf][k][64 + ty4];
            float4 b0 = *(const float4*)&Bs[buf][k][tx4];
            float4 b1 = *(const float4*)&Bs[buf][k][64 + tx4];
            u64t ap[4];
            ap[0] = pk2(a0.x, a0.y); ap[1] = pk2(a0.z, a0.w);
            ap[2] = pk2(a1.x, a1.y); ap[3] = pk2(a1.z, a1.w);
            u64t bd[8];
            bd[0] = pk2(b0.x, b0.x); bd[1] = pk2(b0.y, b0.y);
            bd[2] = pk2(b0.z, b0.z); bd[3] = pk2(b0.w, b0.w);
            bd[4] = pk2(b1.x, b1.x); bd[5] = pk2(b1.y, b1.y);
            bd[6] = pk2(b1.z, b1.z); bd[7] = pk2(b1.w, b1.w);
#pragma unroll
            for (int i = 0; i < 4; i++)
#pragma unroll
                for (int j = 0; j < 8; j++)
                    ffma2(acc[i][j], ap[i], bd[j]);
        }
        if (kt + 1 < nk) {
            int nb = buf ^ 1;
            As[nb][akk + 0][ar] = pa0.x; As[nb][akk + 1][ar] = pa0.y;
            As[nb][akk + 2][ar] = pa0.z; As[nb][akk + 3][ar] = pa0.w;
            As[nb][akk + 4][ar] = pa1.x; As[nb][akk + 5][ar] = pa1.y;
            As[nb][akk + 6][ar] = pa1.z; As[nb][akk + 7][ar] = pa1.w;
            *(float4*)&Bs[nb][br][bcc]     = pb0;
            *(float4*)&Bs[nb][br][bcc + 4] = pb1;
            __syncthreads();
            buf = nb;
        }
    }

    float bv[8];
#pragma unroll
    for (int j = 0; j < 8; j++)
        bv[j] = bih[n0 + ((j < 4) ? (tx4 + j) : (64 + tx4 + j - 4))];
#pragma unroll
    for (int mp = 0; mp < 4; mp++) {
        int r = m0 + ((mp >= 2) ? 64 : 0) + ty4 + (mp & 1) * 2;
        float2 v[8];
#pragma unroll
        for (int j = 0; j < 8; j++) v[j] = upk(acc[mp][j]);
        float4 lo0 = make_float4(v[0].x + bv[0], v[1].x + bv[1], v[2].x + bv[2], v[3].x + bv[3]);
        float4 lo1 = make_float4(v[4].x + bv[4], v[5].x + bv[5], v[6].x + bv[6], v[7].x + bv[7]);
        float4 hi0 = make_float4(v[0].y + bv[0], v[1].y + bv[1], v[2].y + bv[2], v[3].y + bv[3]);
        float4 hi1 = make_float4(v[4].y + bv[4], v[5].y + bv[5], v[6].y + bv[6], v[7].y + bv[7]);
        float* c0 = C + (size_t)r * ldc + n0;
        float* c1 = C + (size_t)(r + 1) * ldc + n0;
        *(float4*)&c0[tx4]      = lo0;
        *(float4*)&c0[64 + tx4] = lo1;
        *(float4*)&c1[tx4]      = hi0;
        *(float4*)&c1[64 + tx4] = hi1;
    }
}

// ---------------- fc GEMM: fp16 2-pass mma.sync ------------------------------
// y[m][n] = sum_k outw[m][k]*fcw[n][k] + fcb[n];  A(fp16) * (Bh + Bl)
#define TSTR 40   // smem row stride in fp16 (conflict-free frag loads)

__global__ __launch_bounds__(256, 2)
void tgemm_fc(const float* __restrict__ bias, float* __restrict__ Cout)
{
    __shared__ uint16_t sA [128 * TSTR];
    __shared__ uint16_t sBh[128 * TSTR];
    __shared__ uint16_t sBl[128 * TSTR];

    const int tid = threadIdx.x;
    const int wid = tid >> 5, lid = tid & 31;
    const int g   = lid >> 2, tig = lid & 3;
    const int wm  = wid & 1;
    const int wn  = wid >> 1;
    const int n0  = blockIdx.x * 128;
    const int m0  = blockIdx.y * 128;

    // fill mapping: thread covers row fr, k-half kh (16 fp16 = 2x uint4)
    const int fr = tid >> 1;
    const int kh = (tid & 1) * 16;
    const uint16_t* aS  = (const uint16_t*)g_outw_h + (size_t)(m0 + fr) * HH_ + kh;
    const uint16_t* bhS = (const uint16_t*)g_fcw_h  + (size_t)(n0 + fr) * HH_ + kh;
    const uint16_t* blS = (const uint16_t*)g_fcw_l  + (size_t)(n0 + fr) * HH_ + kh;
    uint4* aD  = (uint4*)&sA [fr * TSTR + kh];
    uint4* bhD = (uint4*)&sBh[fr * TSTR + kh];
    uint4* blD = (uint4*)&sBl[fr * TSTR + kh];

    float acc[4][4][4];
#pragma unroll
    for (int i = 0; i < 4; i++)
#pragma unroll
        for (int j = 0; j < 4; j++)
#pragma unroll
            for (int q = 0; q < 4; q++) acc[i][j][q] = 0.f;

    for (int kb = 0; kb < HH_; kb += 32) {
        __syncthreads();
        {
            const uint4* p;
            p = (const uint4*)(aS  + kb); aD[0]  = p[0]; aD[1]  = p[1];
            p = (const uint4*)(bhS + kb); bhD[0] = p[0]; bhD[1] = p[1];
            p = (const uint4*)(blS + kb); blD[0] = p[0]; blD[1] = p[1];
        }
        __syncthreads();
#pragma unroll
        for (int k16 = 0; k16 < 32; k16 += 16) {
            uint32_t bh[4][2], bl[4][2];
#pragma unroll
            for (int nf = 0; nf < 4; nf++) {
                int nb = (wn * 32 + nf * 8 + g) * TSTR + k16 + 2 * tig;
                bh[nf][0] = *(const uint32_t*)&sBh[nb];
                bh[nf][1] = *(const uint32_t*)&sBh[nb + 8];
                bl[nf][0] = *(const uint32_t*)&sBl[nb];
                bl[nf][1] = *(const uint32_t*)&sBl[nb + 8];
            }
#pragma unroll
            for (int mf = 0; mf < 4; mf++) {
                int ab = (wm * 64 + mf * 16 + g) * TSTR + k16 + 2 * tig;
                uint32_t ah[4];
                ah[0] = *(const uint32_t*)&sA[ab];
                ah[1] = *(const uint32_t*)&sA[ab + 8 * TSTR];
                ah[2] = *(const uint32_t*)&sA[ab + 8];
                ah[3] = *(const uint32_t*)&sA[ab + 8 * TSTR + 8];
#pragma unroll
                for (int nf = 0; nf < 4; nf++) {
                    mma_hf(acc[mf][nf], ah, bh[nf][0], bh[nf][1]);   // A*Bh
                    mma_hf(acc[mf][nf], ah, bl[nf][0], bl[nf][1]);   // A*Bl
                }
            }
        }
    }

#pragma unroll
    for (int nf = 0; nf < 4; nf++) {
        int col = n0 + wn * 32 + nf * 8 + 2 * tig;
        float2 bb = *(const float2*)&bias[col];
#pragma unroll
        for (int mf = 0; mf < 4; mf++) {
            int row = m0 + wm * 64 + mf * 16 + g;
            float2 v0 = make_float2(acc[mf][nf][0] + bb.x, acc[mf][nf][1] + bb.y);
            float2 v1 = make_float2(acc[mf][nf][2] + bb.x, acc[mf][nf][3] + bb.y);
            *(float2*)&Cout[(size_t)row * VV_ + col]       = v0;
            *(float2*)&Cout[(size_t)(row + 8) * VV_ + col] = v1;
        }
    }
}

// ---------------- attention GEMM (FFMA2) -> fp16 outw ------------------------
__global__ __launch_bounds__(256, 2)
void attn_gemm()
{
    const int n0 = blockIdx.x * 128;
    const int m0 = blockIdx.y * 128;
    const int u  = blockIdx.z;
    const float* A = g_w   + (size_t)u * SS_ * SS_;
    const float* B = g_out + (size_t)u * HH_;
    __half* Ch = g_outw_h + (size_t)u * HH_;
    const int lda = SS_, ldb = UU_ * HH_, ldc = UU_ * HH_;
    const int kmax = (SS_ < m0 + 128) ? SS_ : (m0 + 128);

    __shared__ float As[2][16][128];
    __shared__ float Bs[2][16][128];

    const int tid = threadIdx.x;
    const int tx4 = (tid & 15) * 4;
    const int ty4 = (tid >> 4) * 4;

    const int ar  = tid >> 1;
    const int akk = (tid & 1) * 8;
    const float* aRow = A + (size_t)(m0 + ar) * lda + akk;
    const int br  = tid >> 4;
    const int bcc = (tid & 15) * 8;
    const float* bPtr = B + (size_t)br * ldb + n0 + bcc;

    u64t acc[4][8];
#pragma unroll
    for (int i = 0; i < 4; i++)
#pragma unroll
        for (int j = 0; j < 8; j++) acc[i][j] = 0ULL;

    float4 pa0 = *(const float4*)(aRow);
    float4 pa1 = *(const float4*)(aRow + 4);
    float4 pb0 = *(const float4*)(bPtr);
    float4 pb1 = *(const float4*)(bPtr + 4);
    As[0][akk + 0][ar] = pa0.x; As[0][akk + 1][ar] = pa0.y;
    As[0][akk + 2][ar] = pa0.z; As[0][akk + 3][ar] = pa0.w;
    As[0][akk + 4][ar] = pa1.x; As[0][akk + 5][ar] = pa1.y;
    As[0][akk + 6][ar] = pa1.z; As[0][akk + 7][ar] = pa1.w;
    *(float4*)&Bs[0][br][bcc]     = pb0;
    *(float4*)&Bs[0][br][bcc + 4] = pb1;
    __syncthreads();

    const int nk = kmax >> 4;
    int buf = 0;
    for (int kt = 0; kt < nk; kt++) {
        if (kt + 1 < nk) {
            int kn = (kt + 1) << 4;
            pa0 = *(const float4*)(aRow + kn);
            pa1 = *(const float4*)(aRow + kn + 4);
            pb0 = *(const float4*)(bPtr + (size_t)kn * ldb);
            pb1 = *(const float4*)(bPtr + (size_t)kn * ldb + 4);
        }
#pragma unroll
        for (int k = 0; k < 16; k++) {
            float4 a0 = *(const float4*)&As[buf][k][ty4];
            float4 a1 = *(const float4*)&As[buf][k][64 + ty4];
            float4 b0 = *(const float4*)&Bs[buf][k][tx4];
            float4 b1 = *(const float4*)&Bs[buf][k][64 + tx4];
            u64t ap[4];
            ap[0] = pk2(a0.x, a0.y); ap[1] = pk2(a0.z, a0.w);
            ap[2] = pk2(a1.x, a1.y); ap[3] = pk2(a1.z, a1.w);
            u64t bd[8];
            bd[0] = pk2(b0.x, b0.x); bd[1] = pk2(b0.y, b0.y);
            bd[2] = pk2(b0.z, b0.z); bd[3] = pk2(b0.w, b0.w);
            bd[4] = pk2(b1.x, b1.x); bd[5] = pk2(b1.y, b1.y);
            bd[6] = pk2(b1.z, b1.z); bd[7] = pk2(b1.w, b1.w);
#pragma unroll
            for (int i = 0; i < 4; i++)
#pragma unroll
                for (int j = 0; j < 8; j++)
                    ffma2(acc[i][j], ap[i], bd[j]);
        }
        if (kt + 1 < nk) {
            int nb = buf ^ 1;
            As[nb][akk + 0][ar] = pa0.x; As[nb][akk + 1][ar] = pa0.y;
            As[nb][akk + 2][ar] = pa0.z; As[nb][akk + 3][ar] = pa0.w;
            As[nb][akk + 4][ar] = pa1.x; As[nb][akk + 5][ar] = pa1.y;
            As[nb][akk + 6][ar] = pa1.z; As[nb][akk + 7][ar] = pa1.w;
            *(float4*)&Bs[nb][br][bcc]     = pb0;
            *(float4*)&Bs[nb][br][bcc + 4] = pb1;
            __syncthreads();
            buf = nb;
        }
    }

#pragma unroll
    for (int mp = 0; mp < 4; mp++) {
        int r = m0 + ((mp >= 2) ? 64 : 0) + ty4 + (mp & 1) * 2;
        float2 v[8];
#pragma unroll
        for (int j = 0; j < 8; j++) v[j] = upk(acc[mp][j]);
        float s0 = 1.f / g_sumw[u * SS_ + r];
        float s1 = 1.f / g_sumw[u * SS_ + r + 1];
        float4 lo0 = make_float4(v[0].x * s0, v[1].x * s0, v[2].x * s0, v[3].x * s0);
        float4 lo1 = make_float4(v[4].x * s0, v[5].x * s0, v[6].x * s0, v[7].x * s0);
        float4 hi0 = make_float4(v[0].y * s1, v[1].y * s1, v[2].y * s1, v[3].y * s1);
        float4 hi1 = make_float4(v[4].y * s1, v[5].y * s1, v[6].y * s1, v[7].y * s1);
        size_t b0 = (size_t)r * ldc, b1 = (size_t)(r + 1) * ldc;
        *(uint2*)&Ch[b0 + n0 + tx4]      = cvt4h(lo0);
        *(uint2*)&Ch[b0 + n0 + 64 + tx4] = cvt4h(lo1);
        *(uint2*)&Ch[b1 + n0 + tx4]      = cvt4h(hi0);
        *(uint2*)&Ch[b1 + n0 + 64 + tx4] = cvt4h(hi1);
    }
}

// ---------------- persistent GRU: all 512 steps in ONE kernel ----------------
// R10 version: 128 blocks x 256 threads (2 warps/SMSP for latency hiding),
// per-thread 2u x 6n micro-tile.
__device__ __forceinline__ void grid_barrier(unsigned& target)
{
    __syncthreads();
    if (threadIdx.x == 0) {
        __threadfence();
        atomicAdd(&g_cnt, 1u);
        target += GRU_BLOCKS;
        while (*(volatile unsigned*)&g_cnt < target) { }
        __threadfence();
    }
    __syncthreads();
}

#define ASH_STRIDE 532

__global__ __launch_bounds__(GRU_THREADS)
void gru_persistent(const float* __restrict__ h0,
                    const float* __restrict__ bhh,
                    const int* __restrict__ x)
{
    extern __shared__ float dsm[];
    float* Wsh = dsm;                         // [256][96]
    float* Ash = dsm + 256 * 96;              // [32][ASH_STRIDE] dup pairs

    const int bz = blockIdx.x;
    const int kc = bz & 1;
    const int u0 = ((bz >> 1) & 3) * 32;
    const int n0 = (bz >> 3) * 96;
    const int kbase = kc * 256;

    const int tid = threadIdx.x;
    const int ty = tid >> 4;
    const int tx = tid & 15;

    for (int fi = tid; fi < 256 * 24; fi += GRU_THREADS) {
        int k = fi / 24, c = fi % 24;
        *(float4*)&Wsh[k * 96 + c * 4] =
            *(const float4*)&g_WhhT[(size_t)(kbase + k) * H3_ + n0 + c * 4];
    }

    const int fu = tid >> 3;
    const int fj = (tid & 7) * 4;

    unsigned target = 0;

    for (int st = 0; st < SS_; st++) {
        const float* hp = (st == 0) ? h0 : (g_out + (size_t)(st - 1) * UU_ * HH_);

        {
            const float* hrow = hp + (size_t)(u0 + fu) * HH_ + kbase;
            float* drow = &Ash[fu * ASH_STRIDE];
#pragma unroll
            for (int i = 0; i < 8; i++) {
                int kb = fj + 32 * i;
                float4 v = *(const float4*)&hrow[kb];
                float* d = &drow[2 * kb];
                *(float2*)&d[0] = make_float2(v.x, v.x);
                *(float2*)&d[2] = make_float2(v.y, v.y);
                *(float2*)&d[4] = make_float2(v.z, v.z);
                *(float2*)&d[6] = make_float2(v.w, v.w);
            }
        }
        __syncthreads();

        u64t acc[2][3];
        acc[0][0] = acc[0][1] = acc[0][2] = 0ULL;
        acc[1][0] = acc[1][1] = acc[1][2] = 0ULL;
        const float* arow0 = &Ash[(ty * 2 + 0) * ASH_STRIDE];
        const float* arow1 = &Ash[(ty * 2 + 1) * ASH_STRIDE];
        const float* bcol  = &Wsh[tx * 6];
#pragma unroll 8
        for (int k = 0; k < 256; k++) {
            u64t a0 = *(const u64t*)&arow0[2 * k];
            u64t a1 = *(const u64t*)&arow1[2 * k];
            const float* bk = bcol + k * 96;
            u64t b0 = *(const u64t*)&bk[0];
            u64t b1 = *(const u64t*)&bk[2];
            u64t b2 = *(const u64t*)&bk[4];
            ffma2(acc[0][0], a0, b0); ffma2(acc[0][1], a0, b1); ffma2(acc[0][2], a0, b2);
            ffma2(acc[1][0], a1, b0); ffma2(acc[1][1], a1, b1); ffma2(acc[1][2], a1, b2);
        }
#pragma unroll
        for (int uu = 0; uu < 2; uu++) {
            float* dst = g_ghp + (size_t)(kc * UU_ + u0 + ty * 2 + uu) * H3_ + n0 + tx * 6;
            float2 w0 = upk(acc[uu][0]);
            float2 w1 = upk(acc[uu][1]);
            float2 w2 = upk(acc[uu][2]);
            *(float2*)&dst[0] = w0;
            *(float2*)&dst[2] = w1;
            *(float2*)&dst[4] = w2;
        }

        grid_barrier(target);

#pragma unroll
        for (int e = 0; e < 2; e++) {
            int idx = e * (GRU_BLOCKS * GRU_THREADS) + bz * GRU_THREADS + tid;
            int u = idx >> 9;
            int j = idx & 511;
            const float* p0 = g_ghp + (size_t)u * H3_;
            const float* p1 = g_ghp + (size_t)(UU_ + u) * H3_;
            float hr = p0[j]        + p1[j]        + bhh[j];
            float hz = p0[512 + j]  + p1[512 + j]  + bhh[512 + j];
            float hn = p0[1024 + j] + p1[1024 + j] + bhh[1024 + j];
            // gi gathered from L2-resident P table
            const float* gi = g_P + (size_t)__ldg(&x[st * UU_ + u]) * H3_;
            float r = 1.f / (1.f + __expf(-(gi[j] + hr)));
            float z = 1.f / (1.f + __expf(-(gi[512 + j] + hz)));
            float a = gi[1024 + j] + r * hn;
            float e2 = __expf(2.f * a);
            float n = 1.f - 2.f / (e2 + 1.f);
            float hprev = hp[(size_t)u * HH_ + j];
            g_out[(size_t)st * UU_ * HH_ + idx] = (1.f - z) * n + z * hprev;
        }

        grid_barrier(target);
    }
}

// ---------------- causal spatiotemporal weight matrix ------------------------
__global__ void wmat_kernel()
{
    const int i = blockIdx.x;
    const int u = blockIdx.y;
    const float ti  = g_tT[u * SS_ + i];
    const float sxi = g_sx[u * SS_ + i];
    const float syi = g_sy[u * SS_ + i];

    float lsum = 0.f;
    for (int j = threadIdx.x; j < SS_; j += 256) {
        float wv = 0.f;
        if (j <= i) {
            float dt = ti - g_tT[u * SS_ + j];
            float dx = sxi - g_sx[u * SS_ + j];
            float dy = syi - g_sy[u * SS_ + j];
            float ds = sqrtf(dx * dx + dy * dy);
            wv = __expf(-dt * (F_LT / F_DAY) - F_LS * ds) + 1e-10f;
        }
        g_w[((size_t)u * SS_ + i) * SS_ + j] = wv;
        lsum += wv;
    }
    __shared__ float red[256];
    red[threadIdx.x] = lsum;
    __syncthreads();
    for (int o = 128; o > 0; o >>= 1) {
        if (threadIdx.x < o) red[threadIdx.x] += red[threadIdx.x + o];
        __syncthreads();
    }
    if (threadIdx.x == 0) g_sumw[u * SS_ + i] = red[0];
}

// copy h_last = out[S-1] to tail of d_out
__global__ void hlast_kernel(float* __restrict__ out)
{
    int i = blockIdx.x * blockDim.x + threadIdx.x;
    if (i < UU_ * HH_)
        out[(size_t)SS_ * UU_ * VV_ + i] = g_out[(size_t)(SS_ - 1) * UU_ * HH_ + i];
}

// ---------------- launcher ---------------------------------------------------
extern "C" void kernel_launch(void* const* d_in, const int* in_sizes, int n_in,
                              void* d_out, int out_size)
{
    const int*   x   = (const int*)d_in[0];
    const float* t   = (const float*)d_in[1];
    const float* s   = (const float*)d_in[2];
    // d_in[3] y_t, d_in[4] y_s, d_in[6] active_user: unused by reference
    const float* h0  = (const float*)d_in[5];
    const float* emb = (const float*)d_in[7];
    const float* Wih = (const float*)d_in[8];
    const float* Whh = (const float*)d_in[9];
    const float* bih = (const float*)d_in[10];
    const float* bhh = (const float*)d_in[11];
    const float* fcw = (const float*)d_in[12];
    const float* fcb = (const float*)d_in[13];
    float* out = (float*)d_out;

    static const int GRU_SMEM = (256 * 96 + 32 * ASH_STRIDE) * 4;
    cudaFuncSetAttribute(gru_persistent,
                         cudaFuncAttributeMaxDynamicSharedMemorySize, GRU_SMEM);

    // 1. transposes + fcw fp16 split + t/s relayout + barrier reset
    prep_kernel<<<(VV_ * HH_ + 255) / 256, 256>>>(Wih, Whh, fcw, t, s);

    // 2. P = emb @ Wih^T + bih  (2048x1536x512 — replaces entire gi GEMM)
    pgemm<<<dim3(H3_ / 128, VV_ / 128), 256>>>(emb, bih);

    // 3. GRU recurrence (gathers gi rows from L2-resident P)
    gru_persistent<<<GRU_BLOCKS, GRU_THREADS, GRU_SMEM>>>(h0, bhh, x);

    // 4. causal spatiotemporal weights + row sums
    wmat_kernel<<<dim3(SS_, UU_), 256>>>();

    // 5. out_w = (w @ out) / sum_w  -> fp16 for fc
    attn_gemm<<<dim3(HH_ / 128, SS_ / 128, UU_), 256>>>();

    // 6. y = out_w @ fc_w^T + fc_b  (fp16 2-pass mma.sync)
    tgemm_fc<<<dim3(VV_ / 128, (SS_ * UU_) / 128), 256>>>(fcb, out);

    // 7. h_last
    hlast_kernel<<<(UU_ * HH_ + 255) / 256, 256>>>(out);
}

// round 13
// speedup vs baseline: 1.2334x; 1.0395x over previous
#include <cuda_runtime.h>
#include <cuda_bf16.h>
#include <cuda_fp16.h>
#include <math.h>
#include <stdint.h>

// Problem constants
#define SS_ 512   // sequence
#define UU_ 128   // users (batch)
#define HH_ 512   // hidden
#define H3_ 1536  // 3*H
#define VV_ 2048  // vocab
#define F_DAY 86400.0f
#define F_LT  0.1f
#define F_LS  1.0f

#define GRU_BLOCKS 128
#define GRU_THREADS 256

typedef unsigned long long u64t;

// ---------------- packed fp32x2 helpers (Blackwell FFMA2) --------------------
__device__ __forceinline__ u64t pk2(float lo, float hi) {
    u64t r; asm("mov.b64 %0, {%1, %2};" : "=l"(r) : "f"(lo), "f"(hi)); return r;
}
__device__ __forceinline__ void ffma2(u64t& d, u64t a, u64t b) {
    asm("fma.rn.f32x2 %0, %1, %2, %0;" : "+l"(d) : "l"(a), "l"(b));
}
__device__ __forceinline__ float2 upk(u64t v) {
    float2 r; asm("mov.b64 {%0, %1}, %2;" : "=f"(r.x), "=f"(r.y) : "l"(v)); return r;
}

// ---------------- fp16 mma.sync helpers (standard PTX, works on sm_103) ------
__device__ __forceinline__ void mma_hf(float* d, const uint32_t* a, uint32_t b0, uint32_t b1) {
    asm volatile(
        "mma.sync.aligned.m16n8k16.row.col.f32.f16.f16.f32 "
        "{%0,%1,%2,%3}, {%4,%5,%6,%7}, {%8,%9}, {%0,%1,%2,%3};"
        : "+f"(d[0]), "+f"(d[1]), "+f"(d[2]), "+f"(d[3])
        : "r"(a[0]), "r"(a[1]), "r"(a[2]), "r"(a[3]), "r"(b0), "r"(b1));
}
// pack float4 -> 4 fp16 (uint2)
__device__ __forceinline__ uint2 cvt4h(float4 v) {
    __half2 p0 = __floats2half2_rn(v.x, v.y);
    __half2 p1 = __floats2half2_rn(v.z, v.w);
    uint2 r;
    r.x = *reinterpret_cast<uint32_t*>(&p0);
    r.y = *reinterpret_cast<uint32_t*>(&p1);
    return r;
}

// ---------------- scratch (device globals; allocation is banned) -------------
__device__ float g_P[(size_t)VV_ * H3_];          // P = emb @ Wih^T + bih  (12.6MB, L2)
__device__ float g_out[(size_t)SS_ * UU_ * HH_];  // [S][U][H]  GRU outputs
__device__ __half g_outw_h[(size_t)SS_ * UU_ * HH_];  // outw (fp16)
__device__ float g_w[(size_t)UU_ * SS_ * SS_];    // [U][S][S]  causal weights
__device__ float g_sumw[UU_ * SS_];               // [U][S]
__device__ float g_WihT[HH_ * H3_];               // [K=H][N=3H] for P gemm
__device__ float g_WhhT[HH_ * H3_];               // [K=H][N=3H] for GRU
__device__ __half g_fcw_h[(size_t)VV_ * HH_];     // fc_w fp16
__device__ float g_tT[UU_ * SS_];                 // t transposed [U][S]
__device__ float g_sx[UU_ * SS_];
__device__ float g_sy[UU_ * SS_];
__device__ float g_ghp[2 * UU_ * H3_];            // split-K partials of gh
__device__ unsigned g_cnt;                        // global barrier counter

// ---------------- prep: transposes + fcw fp16 + t/s + barrier reset ----------
__global__ void prep_kernel(const float* __restrict__ Wih,
                            const float* __restrict__ Whh,
                            const float* __restrict__ fcw,
                            const float* __restrict__ t,
                            const float* __restrict__ s)
{
    int idx = blockIdx.x * blockDim.x + threadIdx.x;
    if (idx == 0) g_cnt = 0;                      // reset software barrier each replay
    if (idx < HH_ * H3_) {
        int k = idx / H3_, n = idx % H3_;
        g_WihT[idx] = Wih[(size_t)n * HH_ + k];
        g_WhhT[idx] = Whh[(size_t)n * HH_ + k];
    }
    if (idx < VV_ * HH_) {
        g_fcw_h[idx] = __float2half_rn(fcw[idx]);
    }
    if (idx < UU_ * SS_) {
        int u = idx / SS_, i = idx % SS_;
        g_tT[idx] = t[(size_t)i * UU_ + u];
        g_sx[idx] = s[((size_t)i * UU_ + u) * 2 + 0];
        g_sy[idx] = s[((size_t)i * UU_ + u) * 2 + 1];
    }
}

// ---------------- P GEMM: P = emb @ Wih^T + bih (FFMA2 128x128x16) -----------
__global__ __launch_bounds__(256, 2)
void pgemm(const float* __restrict__ emb, const float* __restrict__ bih)
{
    const int n0 = blockIdx.x * 128;
    const int m0 = blockIdx.y * 128;
    const float* A = emb;     const int lda = HH_;
    const float* B = g_WihT;  const int ldb = H3_;
    float*       C = g_P;     const int ldc = H3_;

    __shared__ float As[2][16][128];
    __shared__ float Bs[2][16][128];

    const int tid = threadIdx.x;
    const int tx4 = (tid & 15) * 4;
    const int ty4 = (tid >> 4) * 4;

    const int ar  = tid >> 1;
    const int akk = (tid & 1) * 8;
    const float* aRow = A + (size_t)(m0 + ar) * lda + akk;
    const int br  = tid >> 4;
    const int bcc = (tid & 15) * 8;
    const float* bPtr = B + (size_t)br * ldb + n0 + bcc;

    u64t acc[4][8];
#pragma unroll
    for (int i = 0; i < 4; i++)
#pragma unroll
        for (int j = 0; j < 8; j++) acc[i][j] = 0ULL;

    float4 pa0 = *(const float4*)(aRow);
    float4 pa1 = *(const float4*)(aRow + 4);
    float4 pb0 = *(const float4*)(bPtr);
    float4 pb1 = *(const float4*)(bPtr + 4);
    As[0][akk + 0][ar] = pa0.x; As[0][akk + 1][ar] = pa0.y;
    As[0][akk + 2][ar] = pa0.z; As[0][akk + 3][ar] = pa0.w;
    As[0][akk + 4][ar] = pa1.x; As[0][akk + 5][ar] = pa1.y;
    As[0][akk + 6][ar] = pa1.z; As[0][akk + 7][ar] = pa1.w;
    *(float4*)&Bs[0][br][bcc]     = pb0;
    *(float4*)&Bs[0][br][bcc + 4] = pb1;
    __syncthreads();

    const int nk = HH_ >> 4;
    int buf = 0;
    for (int kt = 0; kt < nk; kt++) {
        if (kt + 1 < nk) {
            int kn = (kt + 1) << 4;
            pa0 = *(const float4*)(aRow + kn);
            pa1 = *(const float4*)(aRow + kn + 4);
            pb0 = *(const float4*)(bPtr + (size_t)kn * ldb);
            pb1 = *(const float4*)(bPtr + (size_t)kn * ldb + 4);
        }
#pragma unroll
        for (int k = 0; k < 16; k++) {
            float4 a0 = *(const float4*)&As[buf][k][ty4];
            float4 a1 = *(const float4*)&As[buf][k][64 + ty4];
            float4 b0 = *(const float4*)&Bs[buf][k][tx4];
            float4 b1 = *(const float4*)&Bs[buf][k][64 + tx4];
            u64t ap[4];
            ap[0] = pk2(a0.x, a0.y); ap[1] = pk2(a0.z, a0.w);
            ap[2] = pk2(a1.x, a1.y); ap[3] = pk2(a1.z, a1.w);
            u64t bd[8];
            bd[0] = pk2(b0.x, b0.x); bd[1] = pk2(b0.y, b0.y);
            bd[2] = pk2(b0.z, b0.z); bd[3] = pk2(b0.w, b0.w);
            bd[4] = pk2(b1.x, b1.x); bd[5] = pk2(b1.y, b1.y);
            bd[6] = pk2(b1.z, b1.z); bd[7] = pk2(b1.w, b1.w);
#pragma unroll
            for (int i = 0; i < 4; i++)
#pragma unroll
                for (int j = 0; j < 8; j++)
                    ffma2(acc[i][j], ap[i], bd[j]);
        }
        if (kt + 1 < nk) {
            int nb = buf ^ 1;
            As[nb][akk + 0][ar] = pa0.x; As[nb][akk + 1][ar] = pa0.y;
            As[nb][akk + 2][ar] = pa0.z; As[nb][akk + 3][ar] = pa0.w;
            As[nb][akk + 4][ar] = pa1.x; As[nb][akk + 5][ar] = pa1.y;
            As[nb][akk + 6][ar] = pa1.z; As[nb][akk + 7][ar] = pa1.w;
            *(float4*)&Bs[nb][br][bcc]     = pb0;
            *(float4*)&Bs[nb][br][bcc + 4] = pb1;
            __syncthreads();
            buf = nb;
        }
    }

    float bv[8];
#pragma unroll
    for (int j = 0; j < 8; j++)
        bv[j] = bih[n0 + ((j < 4) ? (tx4 + j) : (64 + tx4 + j - 4))];
#pragma unroll
    for (int mp = 0; mp < 4; mp++) {
        int r = m0 + ((mp >= 2) ? 64 : 0) + ty4 + (mp & 1) * 2;
        float2 v[8];
#pragma unroll
        for (int j = 0; j < 8; j++) v[j] = upk(acc[mp][j]);
        float4 lo0 = make_float4(v[0].x + bv[0], v[1].x + bv[1], v[2].x + bv[2], v[3].x + bv[3]);
        float4 lo1 = make_float4(v[4].x + bv[4], v[5].x + bv[5], v[6].x + bv[6], v[7].x + bv[7]);
        float4 hi0 = make_float4(v[0].y + bv[0], v[1].y + bv[1], v[2].y + bv[2], v[3].y + bv[3]);
        float4 hi1 = make_float4(v[4].y + bv[4], v[5].y + bv[5], v[6].y + bv[6], v[7].y + bv[7]);
        float* c0 = C + (size_t)r * ldc + n0;
        float* c1 = C + (size_t)(r + 1) * ldc + n0;
        *(float4*)&c0[tx4]      = lo0;
        *(float4*)&c0[64 + tx4] = lo1;
        *(float4*)&c1[tx4]      = hi0;
        *(float4*)&c1[64 + tx4] = hi1;
    }
}

// ---------------- fc GEMM: fp16 1-pass mma.sync ------------------------------
// y[m][n] = sum_k outw[m][k]*fcw[n][k] + fcb[n]
#define TSTR 40   // smem row stride in fp16 (conflict-free frag loads)

__global__ __launch_bounds__(256, 2)
void tgemm_fc(const float* __restrict__ bias, float* __restrict__ Cout)
{
    __shared__ uint16_t sA [128 * TSTR];
    __shared__ uint16_t sBh[128 * TSTR];

    const int tid = threadIdx.x;
    const int wid = tid >> 5, lid = tid & 31;
    const int g   = lid >> 2, tig = lid & 3;
    const int wm  = wid & 1;
    const int wn  = wid >> 1;
    const int n0  = blockIdx.x * 128;
    const int m0  = blockIdx.y * 128;

    // fill mapping: thread covers row fr, k-half kh (16 fp16 = 2x uint4)
    const int fr = tid >> 1;
    const int kh = (tid & 1) * 16;
    const uint16_t* aS  = (const uint16_t*)g_outw_h + (size_t)(m0 + fr) * HH_ + kh;
    const uint16_t* bhS = (const uint16_t*)g_fcw_h  + (size_t)(n0 + fr) * HH_ + kh;
    uint4* aD  = (uint4*)&sA [fr * TSTR + kh];
    uint4* bhD = (uint4*)&sBh[fr * TSTR + kh];

    float acc[4][4][4];
#pragma unroll
    for (int i = 0; i < 4; i++)
#pragma unroll
        for (int j = 0; j < 4; j++)
#pragma unroll
            for (int q = 0; q < 4; q++) acc[i][j][q] = 0.f;

    for (int kb = 0; kb < HH_; kb += 32) {
        __syncthreads();
        {
            const uint4* p;
            p = (const uint4*)(aS  + kb); aD[0]  = p[0]; aD[1]  = p[1];
            p = (const uint4*)(bhS + kb); bhD[0] = p[0]; bhD[1] = p[1];
        }
        __syncthreads();
#pragma unroll
        for (int k16 = 0; k16 < 32; k16 += 16) {
            uint32_t bh[4][2];
#pragma unroll
            for (int nf = 0; nf < 4; nf++) {
                int nb = (wn * 32 + nf * 8 + g) * TSTR + k16 + 2 * tig;
                bh[nf][0] = *(const uint32_t*)&sBh[nb];
                bh[nf][1] = *(const uint32_t*)&sBh[nb + 8];
            }
#pragma unroll
            for (int mf = 0; mf < 4; mf++) {
                int ab = (wm * 64 + mf * 16 + g) * TSTR + k16 + 2 * tig;
                uint32_t ah[4];
                ah[0] = *(const uint32_t*)&sA[ab];
                ah[1] = *(const uint32_t*)&sA[ab + 8 * TSTR];
                ah[2] = *(const uint32_t*)&sA[ab + 8];
                ah[3] = *(const uint32_t*)&sA[ab + 8 * TSTR + 8];
#pragma unroll
                for (int nf = 0; nf < 4; nf++)
                    mma_hf(acc[mf][nf], ah, bh[nf][0], bh[nf][1]);
            }
        }
    }

#pragma unroll
    for (int nf = 0; nf < 4; nf++) {
        int col = n0 + wn * 32 + nf * 8 + 2 * tig;
        float2 bb = *(const float2*)&bias[col];
#pragma unroll
        for (int mf = 0; mf < 4; mf++) {
            int row = m0 + wm * 64 + mf * 16 + g;
            float2 v0 = make_float2(acc[mf][nf][0] + bb.x, acc[mf][nf][1] + bb.y);
            float2 v1 = make_float2(acc[mf][nf][2] + bb.x, acc[mf][nf][3] + bb.y);
            *(float2*)&Cout[(size_t)row * VV_ + col]       = v0;
            *(float2*)&Cout[(size_t)(row + 8) * VV_ + col] = v1;
        }
    }
}

// ---------------- attention GEMM (FFMA2) -> fp16 outw ------------------------
__global__ __launch_bounds__(256, 2)
void attn_gemm()
{
    const int n0 = blockIdx.x * 128;
    const int m0 = blockIdx.y * 128;
    const int u  = blockIdx.z;
    const float* A = g_w   + (size_t)u * SS_ * SS_;
    const float* B = g_out + (size_t)u * HH_;
    __half* Ch = g_outw_h + (size_t)u * HH_;
    const int lda = SS_, ldb = UU_ * HH_, ldc = UU_ * HH_;
    const int kmax = (SS_ < m0 + 128) ? SS_ : (m0 + 128);

    __shared__ float As[2][16][128];
    __shared__ float Bs[2][16][128];

    const int tid = threadIdx.x;
    const int tx4 = (tid & 15) * 4;
    const int ty4 = (tid >> 4) * 4;

    const int ar  = tid >> 1;
    const int akk = (tid & 1) * 8;
    const float* aRow = A + (size_t)(m0 + ar) * lda + akk;
    const int br  = tid >> 4;
    const int bcc = (tid & 15) * 8;
    const float* bPtr = B + (size_t)br * ldb + n0 + bcc;

    u64t acc[4][8];
#pragma unroll
    for (int i = 0; i < 4; i++)
#pragma unroll
        for (int j = 0; j < 8; j++) acc[i][j] = 0ULL;

    float4 pa0 = *(const float4*)(aRow);
    float4 pa1 = *(const float4*)(aRow + 4);
    float4 pb0 = *(const float4*)(bPtr);
    float4 pb1 = *(const float4*)(bPtr + 4);
    As[0][akk + 0][ar] = pa0.x; As[0][akk + 1][ar] = pa0.y;
    As[0][akk + 2][ar] = pa0.z; As[0][akk + 3][ar] = pa0.w;
    As[0][akk + 4][ar] = pa1.x; As[0][akk + 5][ar] = pa1.y;
    As[0][akk + 6][ar] = pa1.z; As[0][akk + 7][ar] = pa1.w;
    *(float4*)&Bs[0][br][bcc]     = pb0;
    *(float4*)&Bs[0][br][bcc + 4] = pb1;
    __syncthreads();

    const int nk = kmax >> 4;
    int buf = 0;
    for (int kt = 0; kt < nk; kt++) {
        if (kt + 1 < nk) {
            int kn = (kt + 1) << 4;
            pa0 = *(const float4*)(aRow + kn);
            pa1 = *(const float4*)(aRow + kn + 4);
            pb0 = *(const float4*)(bPtr + (size_t)kn * ldb);
            pb1 = *(const float4*)(bPtr + (size_t)kn * ldb + 4);
        }
#pragma unroll
        for (int k = 0; k < 16; k++) {
            float4 a0 = *(const float4*)&As[buf][k][ty4];
            float4 a1 = *(const float4*)&As[buf][k][64 + ty4];
            float4 b0 = *(const float4*)&Bs[buf][k][tx4];
            float4 b1 = *(const float4*)&Bs[buf][k][64 + tx4];
            u64t ap[4];
            ap[0] = pk2(a0.x, a0.y); ap[1] = pk2(a0.z, a0.w);
            ap[2] = pk2(a1.x, a1.y); ap[3] = pk2(a1.z, a1.w);
            u64t bd[8];
            bd[0] = pk2(b0.x, b0.x); bd[1] = pk2(b0.y, b0.y);
            bd[2] = pk2(b0.z, b0.z); bd[3] = pk2(b0.w, b0.w);
            bd[4] = pk2(b1.x, b1.x); bd[5] = pk2(b1.y, b1.y);
            bd[6] = pk2(b1.z, b1.z); bd[7] = pk2(b1.w, b1.w);
#pragma unroll
            for (int i = 0; i < 4; i++)
#pragma unroll
                for (int j = 0; j < 8; j++)
                    ffma2(acc[i][j], ap[i], bd[j]);
        }
        if (kt + 1 < nk) {
            int nb = buf ^ 1;
            As[nb][akk + 0][ar] = pa0.x; As[nb][akk + 1][ar] = pa0.y;
            As[nb][akk + 2][ar] = pa0.z; As[nb][akk + 3][ar] = pa0.w;
            As[nb][akk + 4][ar] = pa1.x; As[nb][akk + 5][ar] = pa1.y;
            As[nb][akk + 6][ar] = pa1.z; As[nb][akk + 7][ar] = pa1.w;
            *(float4*)&Bs[nb][br][bcc]     = pb0;
            *(float4*)&Bs[nb][br][bcc + 4] = pb1;
            __syncthreads();
            buf = nb;
        }
    }

#pragma unroll
    for (int mp = 0; mp < 4; mp++) {
        int r = m0 + ((mp >= 2) ? 64 : 0) + ty4 + (mp & 1) * 2;
        float2 v[8];
#pragma unroll
        for (int j = 0; j < 8; j++) v[j] = upk(acc[mp][j]);
        float s0 = 1.f / g_sumw[u * SS_ + r];
        float s1 = 1.f / g_sumw[u * SS_ + r + 1];
        float4 lo0 = make_float4(v[0].x * s0, v[1].x * s0, v[2].x * s0, v[3].x * s0);
        float4 lo1 = make_float4(v[4].x * s0, v[5].x * s0, v[6].x * s0, v[7].x * s0);
        float4 hi0 = make_float4(v[0].y * s1, v[1].y * s1, v[2].y * s1, v[3].y * s1);
        float4 hi1 = make_float4(v[4].y * s1, v[5].y * s1, v[6].y * s1, v[7].y * s1);
        size_t b0 = (size_t)r * ldc, b1 = (size_t)(r + 1) * ldc;
        *(uint2*)&Ch[b0 + n0 + tx4]      = cvt4h(lo0);
        *(uint2*)&Ch[b0 + n0 + 64 + tx4] = cvt4h(lo1);
        *(uint2*)&Ch[b1 + n0 + tx4]      = cvt4h(hi0);
        *(uint2*)&Ch[b1 + n0 + 64 + tx4] = cvt4h(hi1);
    }
}

// ---------------- persistent GRU: all 512 steps in ONE kernel ----------------
// 128 blocks x 256 threads (2 warps/SMSP for latency hiding), 2u x 6n tiles.
__device__ __forceinline__ void grid_barrier(unsigned& target)
{
    __syncthreads();
    if (threadIdx.x == 0) {
        __threadfence();
        atomicAdd(&g_cnt, 1u);
        target += GRU_BLOCKS;
        while (*(volatile unsigned*)&g_cnt < target) { }
        __threadfence();
    }
    __syncthreads();
}

#define ASH_STRIDE 532

__global__ __launch_bounds__(GRU_THREADS)
void gru_persistent(const float* __restrict__ h0,
                    const float* __restrict__ bhh,
                    const int* __restrict__ x)
{
    extern __shared__ float dsm[];
    float* Wsh = dsm;                         // [256][96]
    float* Ash = dsm + 256 * 96;              // [32][ASH_STRIDE] dup pairs

    const int bz = blockIdx.x;
    const int kc = bz & 1;
    const int u0 = ((bz >> 1) & 3) * 32;
    const int n0 = (bz >> 3) * 96;
    const int kbase = kc * 256;

    const int tid = threadIdx.x;
    const int ty = tid >> 4;
    const int tx = tid & 15;

    for (int fi = tid; fi < 256 * 24; fi += GRU_THREADS) {
        int k = fi / 24, c = fi % 24;
        *(float4*)&Wsh[k * 96 + c * 4] =
            *(const float4*)&g_WhhT[(size_t)(kbase + k) * H3_ + n0 + c * 4];
    }

    const int fu = tid >> 3;
    const int fj = (tid & 7) * 4;

    unsigned target = 0;

    for (int st = 0; st < SS_; st++) {
        const float* hp = (st == 0) ? h0 : (g_out + (size_t)(st - 1) * UU_ * HH_);

        {
            const float* hrow = hp + (size_t)(u0 + fu) * HH_ + kbase;
            float* drow = &Ash[fu * ASH_STRIDE];
#pragma unroll
            for (int i = 0; i < 8; i++) {
                int kb = fj + 32 * i;
                float4 v = *(const float4*)&hrow[kb];
                float* d = &drow[2 * kb];
                *(float2*)&d[0] = make_float2(v.x, v.x);
                *(float2*)&d[2] = make_float2(v.y, v.y);
                *(float2*)&d[4] = make_float2(v.z, v.z);
                *(float2*)&d[6] = make_float2(v.w, v.w);
            }
        }
        __syncthreads();

        u64t acc[2][3];
        acc[0][0] = acc[0][1] = acc[0][2] = 0ULL;
        acc[1][0] = acc[1][1] = acc[1][2] = 0ULL;
        const float* arow0 = &Ash[(ty * 2 + 0) * ASH_STRIDE];
        const float* arow1 = &Ash[(ty * 2 + 1) * ASH_STRIDE];
        const float* bcol  = &Wsh[tx * 6];
#pragma unroll 8
        for (int k = 0; k < 256; k++) {
            u64t a0 = *(const u64t*)&arow0[2 * k];
            u64t a1 = *(const u64t*)&arow1[2 * k];
            const float* bk = bcol + k * 96;
            u64t b0 = *(const u64t*)&bk[0];
            u64t b1 = *(const u64t*)&bk[2];
            u64t b2 = *(const u64t*)&bk[4];
            ffma2(acc[0][0], a0, b0); ffma2(acc[0][1], a0, b1); ffma2(acc[0][2], a0, b2);
            ffma2(acc[1][0], a1, b0); ffma2(acc[1][1], a1, b1); ffma2(acc[1][2], a1, b2);
        }
#pragma unroll
        for (int uu = 0; uu < 2; uu++) {
            float* dst = g_ghp + (size_t)(kc * UU_ + u0 + ty * 2 + uu) * H3_ + n0 + tx * 6;
            float2 w0 = upk(acc[uu][0]);
            float2 w1 = upk(acc[uu][1]);
            float2 w2 = upk(acc[uu][2]);
            *(float2*)&dst[0] = w0;
            *(float2*)&dst[2] = w1;
            *(float2*)&dst[4] = w2;
        }

        grid_barrier(target);

#pragma unroll
        for (int e = 0; e < 2; e++) {
            int idx = e * (GRU_BLOCKS * GRU_THREADS) + bz * GRU_THREADS + tid;
            int u = idx >> 9;
            int j = idx & 511;
            const float* p0 = g_ghp + (size_t)u * H3_;
            const float* p1 = g_ghp + (size_t)(UU_ + u) * H3_;
            float hr = p0[j]        + p1[j]        + bhh[j];
            float hz = p0[512 + j]  + p1[512 + j]  + bhh[512 + j];
            float hn = p0[1024 + j] + p1[1024 + j] + bhh[1024 + j];
            // gi gathered from L2-resident P table
            const float* gi = g_P + (size_t)__ldg(&x[st * UU_ + u]) * H3_;
            float r = 1.f / (1.f + __expf(-(gi[j] + hr)));
            float z = 1.f / (1.f + __expf(-(gi[512 + j] + hz)));
            float a = gi[1024 + j] + r * hn;
            float e2 = __expf(2.f * a);
            float n = 1.f - 2.f / (e2 + 1.f);
            float hprev = hp[(size_t)u * HH_ + j];
            g_out[(size_t)st * UU_ * HH_ + idx] = (1.f - z) * n + z * hprev;
        }

        grid_barrier(target);
    }
}

// ---------------- causal spatiotemporal weight matrix ------------------------
__global__ void wmat_kernel()
{
    const int i = blockIdx.x;
    const int u = blockIdx.y;
    const float ti  = g_tT[u * SS_ + i];
    const float sxi = g_sx[u * SS_ + i];
    const float syi = g_sy[u * SS_ + i];

    float lsum = 0.f;
    for (int j = threadIdx.x; j < SS_; j += 256) {
        float wv = 0.f;
        if (j <= i) {
            float dt = ti - g_tT[u * SS_ + j];
            float dx = sxi - g_sx[u * SS_ + j];
            float dy = syi - g_sy[u * SS_ + j];
            float ds = sqrtf(dx * dx + dy * dy);
            wv = __expf(-dt * (F_LT / F_DAY) - F_LS * ds) + 1e-10f;
        }
        g_w[((size_t)u * SS_ + i) * SS_ + j] = wv;
        lsum += wv;
    }
    __shared__ float red[256];
    red[threadIdx.x] = lsum;
    __syncthreads();
    for (int o = 128; o > 0; o >>= 1) {
        if (threadIdx.x < o) red[threadIdx.x] += red[threadIdx.x + o];
        __syncthreads();
    }
    if (threadIdx.x == 0) g_sumw[u * SS_ + i] = red[0];
}

// copy h_last = out[S-1] to tail of d_out
__global__ void hlast_kernel(float* __restrict__ out)
{
    int i = blockIdx.x * blockDim.x + threadIdx.x;
    if (i < UU_ * HH_)
        out[(size_t)SS_ * UU_ * VV_ + i] = g_out[(size_t)(SS_ - 1) * UU_ * HH_ + i];
}

// ---------------- launcher ---------------------------------------------------
extern "C" void kernel_launch(void* const* d_in, const int* in_sizes, int n_in,
                              void* d_out, int out_size)
{
    const int*   x   = (const int*)d_in[0];
    const float* t   = (const float*)d_in[1];
    const float* s   = (const float*)d_in[2];
    // d_in[3] y_t, d_in[4] y_s, d_in[6] active_user: unused by reference
    const float* h0  = (const float*)d_in[5];
    const float* emb = (const float*)d_in[7];
    const float* Wih = (const float*)d_in[8];
    const float* Whh = (const float*)d_in[9];
    const float* bih = (const float*)d_in[10];
    const float* bhh = (const float*)d_in[11];
    const float* fcw = (const float*)d_in[12];
    const float* fcb = (const float*)d_in[13];
    float* out = (float*)d_out;

    static const int GRU_SMEM = (256 * 96 + 32 * ASH_STRIDE) * 4;
    cudaFuncSetAttribute(gru_persistent,
                         cudaFuncAttributeMaxDynamicSharedMemorySize, GRU_SMEM);

    // 1. transposes + fcw fp16 + t/s relayout + barrier reset
    prep_kernel<<<(VV_ * HH_ + 255) / 256, 256>>>(Wih, Whh, fcw, t, s);

    // 2. P = emb @ Wih^T + bih  (2048x1536x512 — replaces entire gi GEMM)
    pgemm<<<dim3(H3_ / 128, VV_ / 128), 256>>>(emb, bih);

    // 3. GRU recurrence (gathers gi rows from L2-resident P)
    gru_persistent<<<GRU_BLOCKS, GRU_THREADS, GRU_SMEM>>>(h0, bhh, x);

    // 4. causal spatiotemporal weights + row sums
    wmat_kernel<<<dim3(SS_, UU_), 256>>>();

    // 5. out_w = (w @ out) / sum_w  -> fp16 for fc
    attn_gemm<<<dim3(HH_ / 128, SS_ / 128, UU_), 256>>>();

    // 6. y = out_w @ fc_w^T + fc_b  (fp16 1-pass mma.sync)
    tgemm_fc<<<dim3(VV_ / 128, (SS_ * UU_) / 128), 256>>>(fcb, out);

    // 7. h_last
    hlast_kernel<<<(UU_ * HH_ + 255) / 256, 256>>>(out);
}

// round 14
// speedup vs baseline: 2.2440x; 1.8194x over previous
#include <cuda_runtime.h>
#include <cuda_bf16.h>
#include <cuda_fp16.h>
#include <math.h>
#include <stdint.h>

// Problem constants
#define SS_ 512   // sequence
#define UU_ 128   // users (batch)
#define HH_ 512   // hidden
#define H3_ 1536  // 3*H
#define VV_ 2048  // vocab
#define F_DAY 86400.0f
#define F_LT  0.1f
#define F_LS  1.0f

#define GRU_BLOCKS 128
#define GRU_THREADS 256
#define KSTR 264   // GRU smem k-stride in fp16 (conflict-free frag loads)

typedef unsigned long long u64t;

// ---------------- packed fp32x2 helpers (Blackwell FFMA2) --------------------
__device__ __forceinline__ u64t pk2(float lo, float hi) {
    u64t r; asm("mov.b64 %0, {%1, %2};" : "=l"(r) : "f"(lo), "f"(hi)); return r;
}
__device__ __forceinline__ void ffma2(u64t& d, u64t a, u64t b) {
    asm("fma.rn.f32x2 %0, %1, %2, %0;" : "+l"(d) : "l"(a), "l"(b));
}
__device__ __forceinline__ float2 upk(u64t v) {
    float2 r; asm("mov.b64 {%0, %1}, %2;" : "=f"(r.x), "=f"(r.y) : "l"(v)); return r;
}

// ---------------- fp16 mma.sync helpers (standard PTX, works on sm_103) ------
__device__ __forceinline__ void mma_hf(float* d, const uint32_t* a, uint32_t b0, uint32_t b1) {
    asm volatile(
        "mma.sync.aligned.m16n8k16.row.col.f32.f16.f16.f32 "
        "{%0,%1,%2,%3}, {%4,%5,%6,%7}, {%8,%9}, {%0,%1,%2,%3};"
        : "+f"(d[0]), "+f"(d[1]), "+f"(d[2]), "+f"(d[3])
        : "r"(a[0]), "r"(a[1]), "r"(a[2]), "r"(a[3]), "r"(b0), "r"(b1));
}
// pack float4 -> 4 fp16 (uint2)
__device__ __forceinline__ uint2 cvt4h(float4 v) {
    __half2 p0 = __floats2half2_rn(v.x, v.y);
    __half2 p1 = __floats2half2_rn(v.z, v.w);
    uint2 r;
    r.x = *reinterpret_cast<uint32_t*>(&p0);
    r.y = *reinterpret_cast<uint32_t*>(&p1);
    return r;
}
// split float4 into fp16 hi + fp16 residual lo (each packed uint2)
__device__ __forceinline__ void cvt4hl(float4 v, uint2& h, uint2& l) {
    __half2 h01 = __floats2half2_rn(v.x, v.y);
    __half2 h23 = __floats2half2_rn(v.z, v.w);
    h.x = *reinterpret_cast<uint32_t*>(&h01);
    h.y = *reinterpret_cast<uint32_t*>(&h23);
    __half2 l01 = __floats2half2_rn(v.x - __low2float(h01), v.y - __high2float(h01));
    __half2 l23 = __floats2half2_rn(v.z - __low2float(h23), v.w - __high2float(h23));
    l.x = *reinterpret_cast<uint32_t*>(&l01);
    l.y = *reinterpret_cast<uint32_t*>(&l23);
}

// ---------------- scratch (device globals; allocation is banned) -------------
__device__ float g_P[(size_t)VV_ * H3_];          // P = emb @ Wih^T + bih  (12.6MB, L2)
__device__ float g_out[(size_t)SS_ * UU_ * HH_];  // [S][U][H]  GRU outputs
__device__ __half g_outw_h[(size_t)SS_ * UU_ * HH_];  // outw (fp16)
__device__ float g_w[(size_t)UU_ * SS_ * SS_];    // [U][S][S]  causal weights
__device__ float g_sumw[UU_ * SS_];               // [U][S]
__device__ float g_WihT[HH_ * H3_];               // [K=H][N=3H] for P gemm
__device__ __half g_whh_h[(size_t)H3_ * HH_];     // W_hh fp16 hi (original [3H][H])
__device__ __half g_whh_l[(size_t)H3_ * HH_];     // W_hh fp16 lo residual
__device__ __half g_fcw_h[(size_t)VV_ * HH_];     // fc_w fp16
__device__ float g_tT[UU_ * SS_];                 // t transposed [U][S]
__device__ float g_sx[UU_ * SS_];
__device__ float g_sy[UU_ * SS_];
__device__ float g_ghp[2 * UU_ * H3_];            // split-K partials of gh
__device__ unsigned g_cnt;                        // global barrier counter

// ---------------- prep: WihT transpose + Whh/fcw fp16 + t/s + barrier reset --
__global__ void prep_kernel(const float* __restrict__ Wih,
                            const float* __restrict__ Whh,
                            const float* __restrict__ fcw,
                            const float* __restrict__ t,
                            const float* __restrict__ s)
{
    int idx = blockIdx.x * blockDim.x + threadIdx.x;
    if (idx == 0) g_cnt = 0;                      // reset software barrier each replay
    if (idx < HH_ * H3_) {
        int k = idx / H3_, n = idx % H3_;
        g_WihT[idx] = Wih[(size_t)n * HH_ + k];
        // W_hh split (original layout, k-contiguous — what the B-frag wants)
        float f = Whh[idx];
        __half h = __float2half_rn(f);
        g_whh_h[idx] = h;
        g_whh_l[idx] = __float2half_rn(f - __half2float(h));
    }
    if (idx < VV_ * HH_) {
        g_fcw_h[idx] = __float2half_rn(fcw[idx]);
    }
    if (idx < UU_ * SS_) {
        int u = idx / SS_, i = idx % SS_;
        g_tT[idx] = t[(size_t)i * UU_ + u];
        g_sx[idx] = s[((size_t)i * UU_ + u) * 2 + 0];
        g_sy[idx] = s[((size_t)i * UU_ + u) * 2 + 1];
    }
}

// ---------------- P GEMM: P = emb @ Wih^T + bih (FFMA2 128x128x16) -----------
__global__ __launch_bounds__(256, 2)
void pgemm(const float* __restrict__ emb, const float* __restrict__ bih)
{
    const int n0 = blockIdx.x * 128;
    const int m0 = blockIdx.y * 128;
    const float* A = emb;     const int lda = HH_;
    const float* B = g_WihT;  const int ldb = H3_;
    float*       C = g_P;     const int ldc = H3_;

    __shared__ float As[2][16][128];
    __shared__ float Bs[2][16][128];

    const int tid = threadIdx.x;
    const int tx4 = (tid & 15) * 4;
    const int ty4 = (tid >> 4) * 4;

    const int ar  = tid >> 1;
    const int akk = (tid & 1) * 8;
    const float* aRow = A + (size_t)(m0 + ar) * lda + akk;
    const int br  = tid >> 4;
    const int bcc = (tid & 15) * 8;
    const float* bPtr = B + (size_t)br * ldb + n0 + bcc;

    u64t acc[4][8];
#pragma unroll
    for (int i = 0; i < 4; i++)
#pragma unroll
        for (int j = 0; j < 8; j++) acc[i][j] = 0ULL;

    float4 pa0 = *(const float4*)(aRow);
    float4 pa1 = *(const float4*)(aRow + 4);
    float4 pb0 = *(const float4*)(bPtr);
    float4 pb1 = *(const float4*)(bPtr + 4);
    As[0][akk + 0][ar] = pa0.x; As[0][akk + 1][ar] = pa0.y;
    As[0][akk + 2][ar] = pa0.z; As[0][akk + 3][ar] = pa0.w;
    As[0][akk + 4][ar] = pa1.x; As[0][akk + 5][ar] = pa1.y;
    As[0][akk + 6][ar] = pa1.z; As[0][akk + 7][ar] = pa1.w;
    *(float4*)&Bs[0][br][bcc]     = pb0;
    *(float4*)&Bs[0][br][bcc + 4] = pb1;
    __syncthreads();

    const int nk = HH_ >> 4;
    int buf = 0;
    for (int kt = 0; kt < nk; kt++) {
        if (kt + 1 < nk) {
            int kn = (kt + 1) << 4;
            pa0 = *(const float4*)(aRow + kn);
            pa1 = *(const float4*)(aRow + kn + 4);
            pb0 = *(const float4*)(bPtr + (size_t)kn * ldb);
            pb1 = *(const float4*)(bPtr + (size_t)kn * ldb + 4);
        }
#pragma unroll
        for (int k = 0; k < 16; k++) {
            float4 a0 = *(const float4*)&As[buf][k][ty4];
            float4 a1 = *(const float4*)&As[buf][k][64 + ty4];
            float4 b0 = *(const float4*)&Bs[buf][k][tx4];
            float4 b1 = *(const float4*)&Bs[buf][k][64 + tx4];
            u64t ap[4];
            ap[0] = pk2(a0.x, a0.y); ap[1] = pk2(a0.z, a0.w);
            ap[2] = pk2(a1.x, a1.y); ap[3] = pk2(a1.z, a1.w);
            u64t bd[8];
            bd[0] = pk2(b0.x, b0.x); bd[1] = pk2(b0.y, b0.y);
            bd[2] = pk2(b0.z, b0.z); bd[3] = pk2(b0.w, b0.w);
            bd[4] = pk2(b1.x, b1.x); bd[5] = pk2(b1.y, b1.y);
            bd[6] = pk2(b1.z, b1.z); bd[7] = pk2(b1.w, b1.w);
#pragma unroll
            for (int i = 0; i < 4; i++)
#pragma unroll
                for (int j = 0; j < 8; j++)
                    ffma2(acc[i][j], ap[i], bd[j]);
        }
        if (kt + 1 < nk) {
            int nb = buf ^ 1;
            As[nb][akk + 0][ar] = pa0.x; As[nb][akk + 1][ar] = pa0.y;
            As[nb][akk + 2][ar] = pa0.z; As[nb][akk + 3][ar] = pa0.w;
            As[nb][akk + 4][ar] = pa1.x; As[nb][akk + 5][ar] = pa1.y;
            As[nb][akk + 6][ar] = pa1.z; As[nb][akk + 7][ar] = pa1.w;
            *(float4*)&Bs[nb][br][bcc]     = pb0;
            *(float4*)&Bs[nb][br][bcc + 4] = pb1;
            __syncthreads();
            buf = nb;
        }
    }

    float bv[8];
#pragma unroll
    for (int j = 0; j < 8; j++)
        bv[j] = bih[n0 + ((j < 4) ? (tx4 + j) : (64 + tx4 + j - 4))];
#pragma unroll
    for (int mp = 0; mp < 4; mp++) {
        int r = m0 + ((mp >= 2) ? 64 : 0) + ty4 + (mp & 1) * 2;
        float2 v[8];
#pragma unroll
        for (int j = 0; j < 8; j++) v[j] = upk(acc[mp][j]);
        float4 lo0 = make_float4(v[0].x + bv[0], v[1].x + bv[1], v[2].x + bv[2], v[3].x + bv[3]);
        float4 lo1 = make_float4(v[4].x + bv[4], v[5].x + bv[5], v[6].x + bv[6], v[7].x + bv[7]);
        float4 hi0 = make_float4(v[0].y + bv[0], v[1].y + bv[1], v[2].y + bv[2], v[3].y + bv[3]);
        float4 hi1 = make_float4(v[4].y + bv[4], v[5].y + bv[5], v[6].y + bv[6], v[7].y + bv[7]);
        float* c0 = C + (size_t)r * ldc + n0;
        float* c1 = C + (size_t)(r + 1) * ldc + n0;
        *(float4*)&c0[tx4]      = lo0;
        *(float4*)&c0[64 + tx4] = lo1;
        *(float4*)&c1[tx4]      = hi0;
        *(float4*)&c1[64 + tx4] = hi1;
    }
}

// ---------------- fc GEMM: fp16 1-pass mma.sync ------------------------------
#define TSTR 40   // smem row stride in fp16 (conflict-free frag loads)

__global__ __launch_bounds__(256, 2)
void tgemm_fc(const float* __restrict__ bias, float* __restrict__ Cout)
{
    __shared__ uint16_t sA [128 * TSTR];
    __shared__ uint16_t sBh[128 * TSTR];

    const int tid = threadIdx.x;
    const int wid = tid >> 5, lid = tid & 31;
    const int g   = lid >> 2, tig = lid & 3;
    const int wm  = wid & 1;
    const int wn  = wid >> 1;
    const int n0  = blockIdx.x * 128;
    const int m0  = blockIdx.y * 128;

    const int fr = tid >> 1;
    const int kh = (tid & 1) * 16;
    const uint16_t* aS  = (const uint16_t*)g_outw_h + (size_t)(m0 + fr) * HH_ + kh;
    const uint16_t* bhS = (const uint16_t*)g_fcw_h  + (size_t)(n0 + fr) * HH_ + kh;
    uint4* aD  = (uint4*)&sA [fr * TSTR + kh];
    uint4* bhD = (uint4*)&sBh[fr * TSTR + kh];

    float acc[4][4][4];
#pragma unroll
    for (int i = 0; i < 4; i++)
#pragma unroll
        for (int j = 0; j < 4; j++)
#pragma unroll
            for (int q = 0; q < 4; q++) acc[i][j][q] = 0.f;

    for (int kb = 0; kb < HH_; kb += 32) {
        __syncthreads();
        {
            const uint4* p;
            p = (const uint4*)(aS  + kb); aD[0]  = p[0]; aD[1]  = p[1];
            p = (const uint4*)(bhS + kb); bhD[0] = p[0]; bhD[1] = p[1];
        }
        __syncthreads();
#pragma unroll
        for (int k16 = 0; k16 < 32; k16 += 16) {
            uint32_t bh[4][2];
#pragma unroll
            for (int nf = 0; nf < 4; nf++) {
                int nb = (wn * 32 + nf * 8 + g) * TSTR + k16 + 2 * tig;
                bh[nf][0] = *(const uint32_t*)&sBh[nb];
                bh[nf][1] = *(const uint32_t*)&sBh[nb + 8];
            }
#pragma unroll
            for (int mf = 0; mf < 4; mf++) {
                int ab = (wm * 64 + mf * 16 + g) * TSTR + k16 + 2 * tig;
                uint32_t ah[4];
                ah[0] = *(const uint32_t*)&sA[ab];
                ah[1] = *(const uint32_t*)&sA[ab + 8 * TSTR];
                ah[2] = *(const uint32_t*)&sA[ab + 8];
                ah[3] = *(const uint32_t*)&sA[ab + 8 * TSTR + 8];
#pragma unroll
                for (int nf = 0; nf < 4; nf++)
                    mma_hf(acc[mf][nf], ah, bh[nf][0], bh[nf][1]);
            }
        }
    }

#pragma unroll
    for (int nf = 0; nf < 4; nf++) {
        int col = n0 + wn * 32 + nf * 8 + 2 * tig;
        float2 bb = *(const float2*)&bias[col];
#pragma unroll
        for (int mf = 0; mf < 4; mf++) {
            int row = m0 + wm * 64 + mf * 16 + g;
            float2 v0 = make_float2(acc[mf][nf][0] + bb.x, acc[mf][nf][1] + bb.y);
            float2 v1 = make_float2(acc[mf][nf][2] + bb.x, acc[mf][nf][3] + bb.y);
            *(float2*)&Cout[(size_t)row * VV_ + col]       = v0;
            *(float2*)&Cout[(size_t)(row + 8) * VV_ + col] = v1;
        }
    }
}

// ---------------- attention GEMM (FFMA2) -> fp16 outw ------------------------
__global__ __launch_bounds__(256, 2)
void attn_gemm()
{
    const int n0 = blockIdx.x * 128;
    const int m0 = blockIdx.y * 128;
    const int u  = blockIdx.z;
    const float* A = g_w   + (size_t)u * SS_ * SS_;
    const float* B = g_out + (size_t)u * HH_;
    __half* Ch = g_outw_h + (size_t)u * HH_;
    const int lda = SS_, ldb = UU_ * HH_, ldc = UU_ * HH_;
    const int kmax = (SS_ < m0 + 128) ? SS_ : (m0 + 128);

    __shared__ float As[2][16][128];
    __shared__ float Bs[2][16][128];

    const int tid = threadIdx.x;
    const int tx4 = (tid & 15) * 4;
    const int ty4 = (tid >> 4) * 4;

    const int ar  = tid >> 1;
    const int akk = (tid & 1) * 8;
    const float* aRow = A + (size_t)(m0 + ar) * lda + akk;
    const int br  = tid >> 4;
    const int bcc = (tid & 15) * 8;
    const float* bPtr = B + (size_t)br * ldb + n0 + bcc;

    u64t acc[4][8];
#pragma unroll
    for (int i = 0; i < 4; i++)
#pragma unroll
        for (int j = 0; j < 8; j++) acc[i][j] = 0ULL;

    float4 pa0 = *(const float4*)(aRow);
    float4 pa1 = *(const float4*)(aRow + 4);
    float4 pb0 = *(const float4*)(bPtr);
    float4 pb1 = *(const float4*)(bPtr + 4);
    As[0][akk + 0][ar] = pa0.x; As[0][akk + 1][ar] = pa0.y;
    As[0][akk + 2][ar] = pa0.z; As[0][akk + 3][ar] = pa0.w;
    As[0][akk + 4][ar] = pa1.x; As[0][akk + 5][ar] = pa1.y;
    As[0][akk + 6][ar] = pa1.z; As[0][akk + 7][ar] = pa1.w;
    *(float4*)&Bs[0][br][bcc]     = pb0;
    *(float4*)&Bs[0][br][bcc + 4] = pb1;
    __syncthreads();

    const int nk = kmax >> 4;
    int buf = 0;
    for (int kt = 0; kt < nk; kt++) {
        if (kt + 1 < nk) {
            int kn = (kt + 1) << 4;
            pa0 = *(const float4*)(aRow + kn);
            pa1 = *(const float4*)(aRow + kn + 4);
            pb0 = *(const float4*)(bPtr + (size_t)kn * ldb);
            pb1 = *(const float4*)(bPtr + (size_t)kn * ldb + 4);
        }
#pragma unroll
        for (int k = 0; k < 16; k++) {
            float4 a0 = *(const float4*)&As[buf][k][ty4];
            float4 a1 = *(const float4*)&As[buf][k][64 + ty4];
            float4 b0 = *(const float4*)&Bs[buf][k][tx4];
            float4 b1 = *(const float4*)&Bs[buf][k][64 + tx4];
            u64t ap[4];
            ap[0] = pk2(a0.x, a0.y); ap[1] = pk2(a0.z, a0.w);
            ap[2] = pk2(a1.x, a1.y); ap[3] = pk2(a1.z, a1.w);
            u64t bd[8];
            bd[0] = pk2(b0.x, b0.x); bd[1] = pk2(b0.y, b0.y);
            bd[2] = pk2(b0.z, b0.z); bd[3] = pk2(b0.w, b0.w);
            bd[4] = pk2(b1.x, b1.x); bd[5] = pk2(b1.y, b1.y);
            bd[6] = pk2(b1.z, b1.z); bd[7] = pk2(b1.w, b1.w);
#pragma unroll
            for (int i = 0; i < 4; i++)
#pragma unroll
                for (int j = 0; j < 8; j++)
                    ffma2(acc[i][j], ap[i], bd[j]);
        }
        if (kt + 1 < nk) {
            int nb = buf ^ 1;
            As[nb][akk + 0][ar] = pa0.x; As[nb][akk + 1][ar] = pa0.y;
            As[nb][akk + 2][ar] = pa0.z; As[nb][akk + 3][ar] = pa0.w;
            As[nb][akk + 4][ar] = pa1.x; As[nb][akk + 5][ar] = pa1.y;
            As[nb][akk + 6][ar] = pa1.z; As[nb][akk + 7][ar] = pa1.w;
            *(float4*)&Bs[nb][br][bcc]     = pb0;
            *(float4*)&Bs[nb][br][bcc + 4] = pb1;
            __syncthreads();
            buf = nb;
        }
    }

#pragma unroll
    for (int mp = 0; mp < 4; mp++) {
        int r = m0 + ((mp >= 2) ? 64 : 0) + ty4 + (mp & 1) * 2;
        float2 v[8];
#pragma unroll
        for (int j = 0; j < 8; j++) v[j] = upk(acc[mp][j]);
        float s0 = 1.f / g_sumw[u * SS_ + r];
        float s1 = 1.f / g_sumw[u * SS_ + r + 1];
        float4 lo0 = make_float4(v[0].x * s0, v[1].x * s0, v[2].x * s0, v[3].x * s0);
        float4 lo1 = make_float4(v[4].x * s0, v[5].x * s0, v[6].x * s0, v[7].x * s0);
        float4 hi0 = make_float4(v[0].y * s1, v[1].y * s1, v[2].y * s1, v[3].y * s1);
        float4 hi1 = make_float4(v[4].y * s1, v[5].y * s1, v[6].y * s1, v[7].y * s1);
        size_t b0 = (size_t)r * ldc, b1 = (size_t)(r + 1) * ldc;
        *(uint2*)&Ch[b0 + n0 + tx4]      = cvt4h(lo0);
        *(uint2*)&Ch[b0 + n0 + 64 + tx4] = cvt4h(lo1);
        *(uint2*)&Ch[b1 + n0 + tx4]      = cvt4h(hi0);
        *(uint2*)&Ch[b1 + n0 + 64 + tx4] = cvt4h(hi1);
    }
}

// ---------------- persistent GRU: all 512 steps in ONE kernel ----------------
// Phase A now fp16 mma.sync (3-pass hi/lo split — exact to ~2^-21).
// Block: kc(2) x u0(4 of 32) x n0(16 of 96); per block M=32, N=96, K=256.
// Warp w: m-frag (w&1), n-frags 3*(w>>1)..+2.
__device__ __forceinline__ void grid_barrier(unsigned& target)
{
    __syncthreads();
    if (threadIdx.x == 0) {
        __threadfence();
        atomicAdd(&g_cnt, 1u);
        target += GRU_BLOCKS;
        while (*(volatile unsigned*)&g_cnt < target) { }
        __threadfence();
    }
    __syncthreads();
}

__global__ __launch_bounds__(GRU_THREADS)
void gru_persistent(const float* __restrict__ h0,
                    const float* __restrict__ bhh,
                    const int* __restrict__ x)
{
    extern __shared__ uint16_t hsm[];
    uint16_t* WH = hsm;                      // [96][KSTR] W_hh hi
    uint16_t* WL = hsm + 96 * KSTR;          // [96][KSTR] W_hh lo
    uint16_t* HHs = hsm + 2 * 96 * KSTR;     // [32][KSTR] h hi
    uint16_t* HLs = HHs + 32 * KSTR;         // [32][KSTR] h lo

    const int bz = blockIdx.x;
    const int kc = bz & 1;
    const int u0 = ((bz >> 1) & 3) * 32;
    const int n0 = (bz >> 3) * 96;
    const int kbase = kc * 256;

    const int tid = threadIdx.x;
    const int w   = tid >> 5, lid = tid & 31;
    const int g   = lid >> 2, tig = lid & 3;
    const int mf  = w & 1;                   // m-frag (rows 16*mf..+15 of 32)
    const int nb3 = (w >> 1) * 24;           // warp's n base (3 frags of 8)

    // cache W_hh slice [96 n][256 k] fp16 hi/lo once (k-contiguous source)
    for (int fi = tid; fi < 96 * 32; fi += GRU_THREADS) {
        int n = fi >> 5;
        int k8 = (fi & 31) * 8;
        const __half* sh = g_whh_h + (size_t)(n0 + n) * HH_ + kbase + k8;
        const __half* sl = g_whh_l + (size_t)(n0 + n) * HH_ + kbase + k8;
        *(uint4*)&WH[n * KSTR + k8] = *(const uint4*)sh;
        *(uint4*)&WL[n * KSTR + k8] = *(const uint4*)sl;
    }

    const int fu = tid >> 3;                 // staging: row 0..31
    const int fj = (tid & 7) * 4;            // staging: k offset, stride 32

    unsigned target = 0;

    for (int st = 0; st < SS_; st++) {
        const float* hp = (st == 0) ? h0 : (g_out + (size_t)(st - 1) * UU_ * HH_);

        // stage h slice [32][256] -> fp16 hi/lo
        {
            const float* hrow = hp + (size_t)(u0 + fu) * HH_ + kbase;
            uint16_t* dH = &HHs[fu * KSTR];
            uint16_t* dL = &HLs[fu * KSTR];
#pragma unroll
            for (int i = 0; i < 8; i++) {
                int k4 = fj + 32 * i;
                float4 v = *(const float4*)&hrow[k4];
                uint2 hh, ll;
                cvt4hl(v, hh, ll);
                *(uint2*)&dH[k4] = hh;
                *(uint2*)&dL[k4] = ll;
            }
        }
        __syncthreads();

        // ---- phase A: 3-pass fp16 mma over K=256
        float acc[3][4];
#pragma unroll
        for (int f = 0; f < 3; f++)
#pragma unroll
            for (int q = 0; q < 4; q++) acc[f][q] = 0.f;

#pragma unroll 4
        for (int k16 = 0; k16 < 256; k16 += 16) {
            int ab = (mf * 16 + g) * KSTR + k16 + 2 * tig;
            uint32_t ah[4], al[4];
            ah[0] = *(const uint32_t*)&HHs[ab];
            ah[1] = *(const uint32_t*)&HHs[ab + 8 * KSTR];
            ah[2] = *(const uint32_t*)&HHs[ab + 8];
            ah[3] = *(const uint32_t*)&HHs[ab + 8 * KSTR + 8];
            al[0] = *(const uint32_t*)&HLs[ab];
            al[1] = *(const uint32_t*)&HLs[ab + 8 * KSTR];
            al[2] = *(const uint32_t*)&HLs[ab + 8];
            al[3] = *(const uint32_t*)&HLs[ab + 8 * KSTR + 8];
#pragma unroll
            for (int f = 0; f < 3; f++) {
                int nbr = (nb3 + f * 8 + g) * KSTR + k16 + 2 * tig;
                uint32_t bh0 = *(const uint32_t*)&WH[nbr];
                uint32_t bh1 = *(const uint32_t*)&WH[nbr + 8];
                uint32_t bl0 = *(const uint32_t*)&WL[nbr];
                uint32_t bl1 = *(const uint32_t*)&WL[nbr + 8];
                mma_hf(acc[f], ah, bh0, bh1);   // Ah*Bh
                mma_hf(acc[f], al, bh0, bh1);   // Al*Bh
                mma_hf(acc[f], ah, bl0, bl1);   // Ah*Bl
            }
        }

        // write partials: rows u0 + mf*16 + g (+8), cols n0 + nb3 + f*8 + 2tig
#pragma unroll
        for (int f = 0; f < 3; f++) {
            int ncol = n0 + nb3 + f * 8 + 2 * tig;
            int ur = u0 + mf * 16 + g;
            *(float2*)&g_ghp[(size_t)(kc * UU_ + ur) * H3_ + ncol] =
                make_float2(acc[f][0], acc[f][1]);
            *(float2*)&g_ghp[(size_t)(kc * UU_ + ur + 8) * H3_ + ncol] =
                make_float2(acc[f][2], acc[f][3]);
        }

        grid_barrier(target);

        // ---- phase B: reduce split-K, gates, h update -> g_out[st]
#pragma unroll
        for (int e = 0; e < 2; e++) {
            int idx = e * (GRU_BLOCKS * GRU_THREADS) + bz * GRU_THREADS + tid;
            int u = idx >> 9;
            int j = idx & 511;
            const float* p0 = g_ghp + (size_t)u * H3_;
            const float* p1 = g_ghp + (size_t)(UU_ + u) * H3_;
            float hr = p0[j]        + p1[j]        + bhh[j];
            float hz = p0[512 + j]  + p1[512 + j]  + bhh[512 + j];
            float hn = p0[1024 + j] + p1[1024 + j] + bhh[1024 + j];
            const float* gi = g_P + (size_t)__ldg(&x[st * UU_ + u]) * H3_;
            float r = 1.f / (1.f + __expf(-(gi[j] + hr)));
            float z = 1.f / (1.f + __expf(-(gi[512 + j] + hz)));
            float a = gi[1024 + j] + r * hn;
            float e2 = __expf(2.f * a);
            float n = 1.f - 2.f / (e2 + 1.f);
            float hprev = hp[(size_t)u * HH_ + j];
            g_out[(size_t)st * UU_ * HH_ + idx] = (1.f - z) * n + z * hprev;
        }

        grid_barrier(target);
    }
}

// ---------------- causal spatiotemporal weight matrix ------------------------
__global__ void wmat_kernel()
{
    const int i = blockIdx.x;
    const int u = blockIdx.y;
    const float ti  = g_tT[u * SS_ + i];
    const float sxi = g_sx[u * SS_ + i];
    const float syi = g_sy[u * SS_ + i];

    float lsum = 0.f;
    for (int j = threadIdx.x; j < SS_; j += 256) {
        float wv = 0.f;
        if (j <= i) {
            float dt = ti - g_tT[u * SS_ + j];
            float dx = sxi - g_sx[u * SS_ + j];
            float dy = syi - g_sy[u * SS_ + j];
            float ds = sqrtf(dx * dx + dy * dy);
            wv = __expf(-dt * (F_LT / F_DAY) - F_LS * ds) + 1e-10f;
        }
        g_w[((size_t)u * SS_ + i) * SS_ + j] = wv;
        lsum += wv;
    }
    __shared__ float red[256];
    red[threadIdx.x] = lsum;
    __syncthreads();
    for (int o = 128; o > 0; o >>= 1) {
        if (threadIdx.x < o) red[threadIdx.x] += red[threadIdx.x + o];
        __syncthreads();
    }
    if (threadIdx.x == 0) g_sumw[u * SS_ + i] = red[0];
}

// copy h_last = out[S-1] to tail of d_out
__global__ void hlast_kernel(float* __restrict__ out)
{
    int i = blockIdx.x * blockDim.x + threadIdx.x;
    if (i < UU_ * HH_)
        out[(size_t)SS_ * UU_ * VV_ + i] = g_out[(size_t)(SS_ - 1) * UU_ * HH_ + i];
}

// ---------------- launcher ---------------------------------------------------
extern "C" void kernel_launch(void* const* d_in, const int* in_sizes, int n_in,
                              void* d_out, int out_size)
{
    const int*   x   = (const int*)d_in[0];
    const float* t   = (const float*)d_in[1];
    const float* s   = (const float*)d_in[2];
    // d_in[3] y_t, d_in[4] y_s, d_in[6] active_user: unused by reference
    const float* h0  = (const float*)d_in[5];
    const float* emb = (const float*)d_in[7];
    const float* Wih = (const float*)d_in[8];
    const float* Whh = (const float*)d_in[9];
    const float* bih = (const float*)d_in[10];
    const float* bhh = (const float*)d_in[11];
    const float* fcw = (const float*)d_in[12];
    const float* fcb = (const float*)d_in[13];
    float* out = (float*)d_out;

    static const int GRU_SMEM = (2 * 96 * KSTR + 2 * 32 * KSTR) * 2;   // 135168 B
    cudaFuncSetAttribute(gru_persistent,
                         cudaFuncAttributeMaxDynamicSharedMemorySize, GRU_SMEM);

    // 1. WihT transpose + Whh fp16 hi/lo + fcw fp16 + t/s + barrier reset
    prep_kernel<<<(VV_ * HH_ + 255) / 256, 256>>>(Wih, Whh, fcw, t, s);

    // 2. P = emb @ Wih^T + bih  (2048x1536x512 — replaces entire gi GEMM)
    pgemm<<<dim3(H3_ / 128, VV_ / 128), 256>>>(emb, bih);

    // 3. GRU recurrence (phase A = fp16 mma 3-pass; gi gathered from P)
    gru_persistent<<<GRU_BLOCKS, GRU_THREADS, GRU_SMEM>>>(h0, bhh, x);

    // 4. causal spatiotemporal weights + row sums
    wmat_kernel<<<dim3(SS_, UU_), 256>>>();

    // 5. out_w = (w @ out) / sum_w  -> fp16 for fc
    attn_gemm<<<dim3(HH_ / 128, SS_ / 128, UU_), 256>>>();

    // 6. y = out_w @ fc_w^T + fc_b  (fp16 1-pass mma.sync)
    tgemm_fc<<<dim3(VV_ / 128, (SS_ * UU_) / 128), 256>>>(fcb, out);

    // 7. h_last
    hlast_kernel<<<(UU_ * HH_ + 255) / 256, 256>>>(out);
}

// round 16
// speedup vs baseline: 2.3431x; 1.0442x over previous
#include <cuda_runtime.h>
#include <cuda_bf16.h>
#include <cuda_fp16.h>
#include <math.h>
#include <stdint.h>

// Problem constants
#define SS_ 512   // sequence
#define UU_ 128   // users (batch)
#define HH_ 512   // hidden
#define H3_ 1536  // 3*H
#define VV_ 2048  // vocab
#define F_DAY 86400.0f
#define F_LT  0.1f
#define F_LS  1.0f

#define GRU_BLOCKS 128
#define GRU_THREADS 256
#define KSTR 264   // GRU smem k-stride in fp16 (conflict-free frag loads)

typedef unsigned long long u64t;

// ---------------- packed fp32x2 helpers (Blackwell FFMA2) --------------------
__device__ __forceinline__ u64t pk2(float lo, float hi) {
    u64t r; asm("mov.b64 %0, {%1, %2};" : "=l"(r) : "f"(lo), "f"(hi)); return r;
}
__device__ __forceinline__ void ffma2(u64t& d, u64t a, u64t b) {
    asm("fma.rn.f32x2 %0, %1, %2, %0;" : "+l"(d) : "l"(a), "l"(b));
}
__device__ __forceinline__ float2 upk(u64t v) {
    float2 r; asm("mov.b64 {%0, %1}, %2;" : "=f"(r.x), "=f"(r.y) : "l"(v)); return r;
}

// ---------------- fp16 mma.sync helpers (standard PTX, works on sm_103) ------
__device__ __forceinline__ void mma_hf(float* d, const uint32_t* a, uint32_t b0, uint32_t b1) {
    asm volatile(
        "mma.sync.aligned.m16n8k16.row.col.f32.f16.f16.f32 "
        "{%0,%1,%2,%3}, {%4,%5,%6,%7}, {%8,%9}, {%0,%1,%2,%3};"
        : "+f"(d[0]), "+f"(d[1]), "+f"(d[2]), "+f"(d[3])
        : "r"(a[0]), "r"(a[1]), "r"(a[2]), "r"(a[3]), "r"(b0), "r"(b1));
}
// pack float4 -> 4 fp16 (uint2)
__device__ __forceinline__ uint2 cvt4h(float4 v) {
    __half2 p0 = __floats2half2_rn(v.x, v.y);
    __half2 p1 = __floats2half2_rn(v.z, v.w);
    uint2 r;
    r.x = *reinterpret_cast<uint32_t*>(&p0);
    r.y = *reinterpret_cast<uint32_t*>(&p1);
    return r;
}
// split float4 into fp16 hi + fp16 residual lo (each packed uint2)
__device__ __forceinline__ void cvt4hl(float4 v, uint2& h, uint2& l) {
    __half2 h01 = __floats2half2_rn(v.x, v.y);
    __half2 h23 = __floats2half2_rn(v.z, v.w);
    h.x = *reinterpret_cast<uint32_t*>(&h01);
    h.y = *reinterpret_cast<uint32_t*>(&h23);
    __half2 l01 = __floats2half2_rn(v.x - __low2float(h01), v.y - __high2float(h01));
    __half2 l23 = __floats2half2_rn(v.z - __low2float(h23), v.w - __high2float(h23));
    l.x = *reinterpret_cast<uint32_t*>(&l01);
    l.y = *reinterpret_cast<uint32_t*>(&l23);
}

// ---------------- scratch (device globals; allocation is banned) -------------
__device__ float g_P[(size_t)VV_ * H3_];          // P = emb @ Wih^T + bih  (12.6MB, L2)
__device__ float g_out[(size_t)SS_ * UU_ * HH_];  // [S][U][H]  GRU outputs
__device__ __half g_outT_h[(size_t)UU_ * HH_ * SS_];  // out transposed fp16 [U][H][S]
__device__ __half g_outw_h[(size_t)SS_ * UU_ * HH_];  // outw (fp16)
__device__ __half g_w_h[(size_t)UU_ * SS_ * SS_]; // [U][S][S]  causal weights (fp16)
__device__ float g_sumw[UU_ * SS_];               // [U][S]
__device__ float g_WihT[HH_ * H3_];               // [K=H][N=3H] for P gemm
__device__ __half g_whh_h[(size_t)H3_ * HH_];     // W_hh fp16 hi (original [3H][H])
__device__ __half g_whh_l[(size_t)H3_ * HH_];     // W_hh fp16 lo residual
__device__ __half g_fcw_h[(size_t)VV_ * HH_];     // fc_w fp16
__device__ float g_tT[UU_ * SS_];                 // t transposed [U][S]
__device__ float g_sx[UU_ * SS_];
__device__ float g_sy[UU_ * SS_];
__device__ float g_ghp[2 * UU_ * H3_];            // split-K partials of gh
__device__ unsigned g_cnt;                        // global barrier counter

// ---------------- prep: WihT transpose + Whh/fcw fp16 + t/s + barrier reset --
__global__ void prep_kernel(const float* __restrict__ Wih,
                            const float* __restrict__ Whh,
                            const float* __restrict__ fcw,
                            const float* __restrict__ t,
                            const float* __restrict__ s)
{
    int idx = blockIdx.x * blockDim.x + threadIdx.x;
    if (idx == 0) g_cnt = 0;                      // reset software barrier each replay
    if (idx < HH_ * H3_) {
        int k = idx / H3_, n = idx % H3_;
        g_WihT[idx] = Wih[(size_t)n * HH_ + k];
        float f = Whh[idx];
        __half h = __float2half_rn(f);
        g_whh_h[idx] = h;
        g_whh_l[idx] = __float2half_rn(f - __half2float(h));
    }
    if (idx < VV_ * HH_) {
        g_fcw_h[idx] = __float2half_rn(fcw[idx]);
    }
    if (idx < UU_ * SS_) {
        int u = idx / SS_, i = idx % SS_;
        g_tT[idx] = t[(size_t)i * UU_ + u];
        g_sx[idx] = s[((size_t)i * UU_ + u) * 2 + 0];
        g_sy[idx] = s[((size_t)i * UU_ + u) * 2 + 1];
    }
}

// ---------------- P GEMM: P = emb @ Wih^T + bih (FFMA2 128x128x16) -----------
__global__ __launch_bounds__(256, 2)
void pgemm(const float* __restrict__ emb, const float* __restrict__ bih)
{
    const int n0 = blockIdx.x * 128;
    const int m0 = blockIdx.y * 128;
    const float* A = emb;     const int lda = HH_;
    const float* B = g_WihT;  const int ldb = H3_;
    float*       C = g_P;     const int ldc = H3_;

    __shared__ float As[2][16][128];
    __shared__ float Bs[2][16][128];

    const int tid = threadIdx.x;
    const int tx4 = (tid & 15) * 4;
    const int ty4 = (tid >> 4) * 4;

    const int ar  = tid >> 1;
    const int akk = (tid & 1) * 8;
    const float* aRow = A + (size_t)(m0 + ar) * lda + akk;
    const int br  = tid >> 4;
    const int bcc = (tid & 15) * 8;
    const float* bPtr = B + (size_t)br * ldb + n0 + bcc;

    u64t acc[4][8];
#pragma unroll
    for (int i = 0; i < 4; i++)
#pragma unroll
        for (int j = 0; j < 8; j++) acc[i][j] = 0ULL;

    float4 pa0 = *(const float4*)(aRow);
    float4 pa1 = *(const float4*)(aRow + 4);
    float4 pb0 = *(const float4*)(bPtr);
    float4 pb1 = *(const float4*)(bPtr + 4);
    As[0][akk + 0][ar] = pa0.x; As[0][akk + 1][ar] = pa0.y;
    As[0][akk + 2][ar] = pa0.z; As[0][akk + 3][ar] = pa0.w;
    As[0][akk + 4][ar] = pa1.x; As[0][akk + 5][ar] = pa1.y;
    As[0][akk + 6][ar] = pa1.z; As[0][akk + 7][ar] = pa1.w;
    *(float4*)&Bs[0][br][bcc]     = pb0;
    *(float4*)&Bs[0][br][bcc + 4] = pb1;
    __syncthreads();

    const int nk = HH_ >> 4;
    int buf = 0;
    for (int kt = 0; kt < nk; kt++) {
        if (kt + 1 < nk) {
            int kn = (kt + 1) << 4;
            pa0 = *(const float4*)(aRow + kn);
            pa1 = *(const float4*)(aRow + kn + 4);
            pb0 = *(const float4*)(bPtr + (size_t)kn * ldb);
            pb1 = *(const float4*)(bPtr + (size_t)kn * ldb + 4);
        }
#pragma unroll
        for (int k = 0; k < 16; k++) {
            float4 a0 = *(const float4*)&As[buf][k][ty4];
            float4 a1 = *(const float4*)&As[buf][k][64 + ty4];
            float4 b0 = *(const float4*)&Bs[buf][k][tx4];
            float4 b1 = *(const float4*)&Bs[buf][k][64 + tx4];
            u64t ap[4];
            ap[0] = pk2(a0.x, a0.y); ap[1] = pk2(a0.z, a0.w);
            ap[2] = pk2(a1.x, a1.y); ap[3] = pk2(a1.z, a1.w);
            u64t bd[8];
            bd[0] = pk2(b0.x, b0.x); bd[1] = pk2(b0.y, b0.y);
            bd[2] = pk2(b0.z, b0.z); bd[3] = pk2(b0.w, b0.w);
            bd[4] = pk2(b1.x, b1.x); bd[5] = pk2(b1.y, b1.y);
            bd[6] = pk2(b1.z, b1.z); bd[7] = pk2(b1.w, b1.w);
#pragma unroll
            for (int i = 0; i < 4; i++)
#pragma unroll
                for (int j = 0; j < 8; j++)
                    ffma2(acc[i][j], ap[i], bd[j]);
        }
        if (kt + 1 < nk) {
            int nb = buf ^ 1;
            As[nb][akk + 0][ar] = pa0.x; As[nb][akk + 1][ar] = pa0.y;
            As[nb][akk + 2][ar] = pa0.z; As[nb][akk + 3][ar] = pa0.w;
            As[nb][akk + 4][ar] = pa1.x; As[nb][akk + 5][ar] = pa1.y;
            As[nb][akk + 6][ar] = pa1.z; As[nb][akk + 7][ar] = pa1.w;
            *(float4*)&Bs[nb][br][bcc]     = pb0;
            *(float4*)&Bs[nb][br][bcc + 4] = pb1;
            __syncthreads();
            buf = nb;
        }
    }

    float bv[8];
#pragma unroll
    for (int j = 0; j < 8; j++)
        bv[j] = bih[n0 + ((j < 4) ? (tx4 + j) : (64 + tx4 + j - 4))];
#pragma unroll
    for (int mp = 0; mp < 4; mp++) {
        int r = m0 + ((mp >= 2) ? 64 : 0) + ty4 + (mp & 1) * 2;
        float2 v[8];
#pragma unroll
        for (int j = 0; j < 8; j++) v[j] = upk(acc[mp][j]);
        float4 lo0 = make_float4(v[0].x + bv[0], v[1].x + bv[1], v[2].x + bv[2], v[3].x + bv[3]);
        float4 lo1 = make_float4(v[4].x + bv[4], v[5].x + bv[5], v[6].x + bv[6], v[7].x + bv[7]);
        float4 hi0 = make_float4(v[0].y + bv[0], v[1].y + bv[1], v[2].y + bv[2], v[3].y + bv[3]);
        float4 hi1 = make_float4(v[4].y + bv[4], v[5].y + bv[5], v[6].y + bv[6], v[7].y + bv[7]);
        float* c0 = C + (size_t)r * ldc + n0;
        float* c1 = C + (size_t)(r + 1) * ldc + n0;
        *(float4*)&c0[tx4]      = lo0;
        *(float4*)&c0[64 + tx4] = lo1;
        *(float4*)&c1[tx4]      = hi0;
        *(float4*)&c1[64 + tx4] = hi1;
    }
}

// ---------------- fc GEMM: fp16 1-pass mma.sync ------------------------------
#define TSTR 40   // smem row stride in fp16 (conflict-free frag loads)

__global__ __launch_bounds__(256, 2)
void tgemm_fc(const float* __restrict__ bias, float* __restrict__ Cout)
{
    __shared__ uint16_t sA [128 * TSTR];
    __shared__ uint16_t sBh[128 * TSTR];

    const int tid = threadIdx.x;
    const int wid = tid >> 5, lid = tid & 31;
    const int g   = lid >> 2, tig = lid & 3;
    const int wm  = wid & 1;
    const int wn  = wid >> 1;
    const int n0  = blockIdx.x * 128;
    const int m0  = blockIdx.y * 128;

    const int fr = tid >> 1;
    const int kh = (tid & 1) * 16;
    const uint16_t* aS  = (const uint16_t*)g_outw_h + (size_t)(m0 + fr) * HH_ + kh;
    const uint16_t* bhS = (const uint16_t*)g_fcw_h  + (size_t)(n0 + fr) * HH_ + kh;
    uint4* aD  = (uint4*)&sA [fr * TSTR + kh];
    uint4* bhD = (uint4*)&sBh[fr * TSTR + kh];

    float acc[4][4][4];
#pragma unroll
    for (int i = 0; i < 4; i++)
#pragma unroll
        for (int j = 0; j < 4; j++)
#pragma unroll
            for (int q = 0; q < 4; q++) acc[i][j][q] = 0.f;

    for (int kb = 0; kb < HH_; kb += 32) {
        __syncthreads();
        {
            const uint4* p;
            p = (const uint4*)(aS  + kb); aD[0]  = p[0]; aD[1]  = p[1];
            p = (const uint4*)(bhS + kb); bhD[0] = p[0]; bhD[1] = p[1];
        }
        __syncthreads();
#pragma unroll
        for (int k16 = 0; k16 < 32; k16 += 16) {
            uint32_t bh[4][2];
#pragma unroll
            for (int nf = 0; nf < 4; nf++) {
                int nb = (wn * 32 + nf * 8 + g) * TSTR + k16 + 2 * tig;
                bh[nf][0] = *(const uint32_t*)&sBh[nb];
                bh[nf][1] = *(const uint32_t*)&sBh[nb + 8];
            }
#pragma unroll
            for (int mf = 0; mf < 4; mf++) {
                int ab = (wm * 64 + mf * 16 + g) * TSTR + k16 + 2 * tig;
                uint32_t ah[4];
                ah[0] = *(const uint32_t*)&sA[ab];
                ah[1] = *(const uint32_t*)&sA[ab + 8 * TSTR];
                ah[2] = *(const uint32_t*)&sA[ab + 8];
                ah[3] = *(const uint32_t*)&sA[ab + 8 * TSTR + 8];
#pragma unroll
                for (int nf = 0; nf < 4; nf++)
                    mma_hf(acc[mf][nf], ah, bh[nf][0], bh[nf][1]);
            }
        }
    }

#pragma unroll
    for (int nf = 0; nf < 4; nf++) {
        int col = n0 + wn * 32 + nf * 8 + 2 * tig;
        float2 bb = *(const float2*)&bias[col];
#pragma unroll
        for (int mf = 0; mf < 4; mf++) {
            int row = m0 + wm * 64 + mf * 16 + g;
            float2 v0 = make_float2(acc[mf][nf][0] + bb.x, acc[mf][nf][1] + bb.y);
            float2 v1 = make_float2(acc[mf][nf][2] + bb.x, acc[mf][nf][3] + bb.y);
            *(float2*)&Cout[(size_t)row * VV_ + col]       = v0;
            *(float2*)&Cout[(size_t)(row + 8) * VV_ + col] = v1;
        }
    }
}

// ---------------- out transpose: g_out [S][U][H] f32 -> g_outT [U][H][S] fp16 -
__global__ void outT_kernel()
{
    __shared__ __half tile[32][33];
    const int j0 = blockIdx.x * 32;
    const int h0 = blockIdx.y * 32;
    const int u  = blockIdx.z;
    const int tx = threadIdx.x, ty = threadIdx.y;   // 32 x 8
#pragma unroll
    for (int q = 0; q < 4; q++) {
        int j = j0 + ty + q * 8;
        tile[ty + q * 8][tx] =
            __float2half_rn(g_out[((size_t)j * UU_ + u) * HH_ + h0 + tx]);
    }
    __syncthreads();
#pragma unroll
    for (int q = 0; q < 4; q++) {
        int h = h0 + ty + q * 8;
        g_outT_h[((size_t)u * HH_ + h) * SS_ + j0 + tx] = tile[tx][ty + q * 8];
    }
}

// ---------------- attention GEMM: fp16 1-pass mma.sync -----------------------
// out_w[i][u][:] = (sum_j w[u][i][j] * out[j][u][:]) / sumw[u][i]
// A = g_w_h[u] [i][j] (k=j contiguous), B = g_outT_h[u] [h][j] (k=j contiguous)
__global__ __launch_bounds__(256, 2)
void attn_gemm_h()
{
    __shared__ uint16_t sA[128 * TSTR];
    __shared__ uint16_t sB[128 * TSTR];

    const int tid = threadIdx.x;
    const int wid = tid >> 5, lid = tid & 31;
    const int g   = lid >> 2, tig = lid & 3;
    const int wm  = wid & 1;
    const int wn  = wid >> 1;
    const int n0  = blockIdx.x * 128;   // h
    const int m0  = blockIdx.y * 128;   // i
    const int u   = blockIdx.z;
    const int kmax = m0 + 128;          // triangular K limit

    const int fr = tid >> 1;
    const int kh = (tid & 1) * 16;
    const uint16_t* aS = (const uint16_t*)g_w_h   + ((size_t)u * SS_ + m0 + fr) * SS_ + kh;
    const uint16_t* bS = (const uint16_t*)g_outT_h + ((size_t)u * HH_ + n0 + fr) * SS_ + kh;
    uint4* aD = (uint4*)&sA[fr * TSTR + kh];
    uint4* bD = (uint4*)&sB[fr * TSTR + kh];

    float acc[4][4][4];
#pragma unroll
    for (int i = 0; i < 4; i++)
#pragma unroll
        for (int j = 0; j < 4; j++)
#pragma unroll
            for (int q = 0; q < 4; q++) acc[i][j][q] = 0.f;

    for (int kb = 0; kb < kmax; kb += 32) {
        __syncthreads();
        {
            const uint4* p;
            p = (const uint4*)(aS + kb); aD[0] = p[0]; aD[1] = p[1];
            p = (const uint4*)(bS + kb); bD[0] = p[0]; bD[1] = p[1];
        }
        __syncthreads();
#pragma unroll
        for (int k16 = 0; k16 < 32; k16 += 16) {
            uint32_t bh[4][2];
#pragma unroll
            for (int nf = 0; nf < 4; nf++) {
                int nb = (wn * 32 + nf * 8 + g) * TSTR + k16 + 2 * tig;
                bh[nf][0] = *(const uint32_t*)&sB[nb];
                bh[nf][1] = *(const uint32_t*)&sB[nb + 8];
            }
#pragma unroll
            for (int mf = 0; mf < 4; mf++) {
                int ab = (wm * 64 + mf * 16 + g) * TSTR + k16 + 2 * tig;
                uint32_t ah[4];
                ah[0] = *(const uint32_t*)&sA[ab];
                ah[1] = *(const uint32_t*)&sA[ab + 8 * TSTR];
                ah[2] = *(const uint32_t*)&sA[ab + 8];
                ah[3] = *(const uint32_t*)&sA[ab + 8 * TSTR + 8];
#pragma unroll
                for (int nf = 0; nf < 4; nf++)
                    mma_hf(acc[mf][nf], ah, bh[nf][0], bh[nf][1]);
            }
        }
    }

    // epilogue: scale by 1/sumw, write fp16 outw [S][U][H]
#pragma unroll
    for (int mf = 0; mf < 4; mf++) {
        int row0 = m0 + wm * 64 + mf * 16 + g;
        float s0 = 1.f / g_sumw[u * SS_ + row0];
        float s1 = 1.f / g_sumw[u * SS_ + row0 + 8];
        __half* c0 = g_outw_h + ((size_t)row0 * UU_ + u) * HH_;
        __half* c1 = g_outw_h + ((size_t)(row0 + 8) * UU_ + u) * HH_;
#pragma unroll
        for (int nf = 0; nf < 4; nf++) {
            int col = n0 + wn * 32 + nf * 8 + 2 * tig;
            __half2 v0 = __floats2half2_rn(acc[mf][nf][0] * s0, acc[mf][nf][1] * s0);
            __half2 v1 = __floats2half2_rn(acc[mf][nf][2] * s1, acc[mf][nf][3] * s1);
            *(__half2*)&c0[col] = v0;
            *(__half2*)&c1[col] = v1;
        }
    }
}

// ---------------- persistent GRU: all 512 steps in ONE kernel ----------------
__device__ __forceinline__ void grid_barrier(unsigned& target)
{
    __syncthreads();
    if (threadIdx.x == 0) {
        __threadfence();
        atomicAdd(&g_cnt, 1u);
        target += GRU_BLOCKS;
        while (*(volatile unsigned*)&g_cnt < target) { }
        __threadfence();
    }
    __syncthreads();
}

__global__ __launch_bounds__(GRU_THREADS)
void gru_persistent(const float* __restrict__ h0,
                    const float* __restrict__ bhh,
                    const int* __restrict__ x)
{
    extern __shared__ uint16_t hsm[];
    uint16_t* WH = hsm;                      // [96][KSTR] W_hh hi
    uint16_t* WL = hsm + 96 * KSTR;          // [96][KSTR] W_hh lo
    uint16_t* HHs = hsm + 2 * 96 * KSTR;     // [32][KSTR] h hi
    uint16_t* HLs = HHs + 32 * KSTR;         // [32][KSTR] h lo

    const int bz = blockIdx.x;
    const int kc = bz & 1;
    const int u0 = ((bz >> 1) & 3) * 32;
    const int n0 = (bz >> 3) * 96;
    const int kbase = kc * 256;

    const int tid = threadIdx.x;
    const int w   = tid >> 5, lid = tid & 31;
    const int g   = lid >> 2, tig = lid & 3;
    const int mf  = w & 1;
    const int nb3 = (w >> 1) * 24;

    for (int fi = tid; fi < 96 * 32; fi += GRU_THREADS) {
        int n = fi >> 5;
        int k8 = (fi & 31) * 8;
        const __half* sh = g_whh_h + (size_t)(n0 + n) * HH_ + kbase + k8;
        const __half* sl = g_whh_l + (size_t)(n0 + n) * HH_ + kbase + k8;
        *(uint4*)&WH[n * KSTR + k8] = *(const uint4*)sh;
        *(uint4*)&WL[n * KSTR + k8] = *(const uint4*)sl;
    }

    const int fu = tid >> 3;
    const int fj = (tid & 7) * 4;

    unsigned target = 0;

    for (int st = 0; st < SS_; st++) {
        const float* hp = (st == 0) ? h0 : (g_out + (size_t)(st - 1) * UU_ * HH_);

        {
            const float* hrow = hp + (size_t)(u0 + fu) * HH_ + kbase;
            uint16_t* dH = &HHs[fu * KSTR];
            uint16_t* dL = &HLs[fu * KSTR];
#pragma unroll
            for (int i = 0; i < 8; i++) {
                int k4 = fj + 32 * i;
                float4 v = *(const float4*)&hrow[k4];
                uint2 hh, ll;
                cvt4hl(v, hh, ll);
                *(uint2*)&dH[k4] = hh;
                *(uint2*)&dL[k4] = ll;
            }
        }
        __syncthreads();

        float acc[3][4];
#pragma unroll
        for (int f = 0; f < 3; f++)
#pragma unroll
            for (int q = 0; q < 4; q++) acc[f][q] = 0.f;

#pragma unroll 4
        for (int k16 = 0; k16 < 256; k16 += 16) {
            int ab = (mf * 16 + g) * KSTR + k16 + 2 * tig;
            uint32_t ah[4], al[4];
            ah[0] = *(const uint32_t*)&HHs[ab];
            ah[1] = *(const uint32_t*)&HHs[ab + 8 * KSTR];
            ah[2] = *(const uint32_t*)&HHs[ab + 8];
            ah[3] = *(const uint32_t*)&HHs[ab + 8 * KSTR + 8];
            al[0] = *(const uint32_t*)&HLs[ab];
            al[1] = *(const uint32_t*)&HLs[ab + 8 * KSTR];
            al[2] = *(const uint32_t*)&HLs[ab + 8];
            al[3] = *(const uint32_t*)&HLs[ab + 8 * KSTR + 8];
#pragma unroll
            for (int f = 0; f < 3; f++) {
                int nbr = (nb3 + f * 8 + g) * KSTR + k16 + 2 * tig;
                uint32_t bh0 = *(const uint32_t*)&WH[nbr];
                uint32_t bh1 = *(const uint32_t*)&WH[nbr + 8];
                uint32_t bl0 = *(const uint32_t*)&WL[nbr];
                uint32_t bl1 = *(const uint32_t*)&WL[nbr + 8];
                mma_hf(acc[f], ah, bh0, bh1);   // Ah*Bh
                mma_hf(acc[f], al, bh0, bh1);   // Al*Bh
                mma_hf(acc[f], ah, bl0, bl1);   // Ah*Bl
            }
        }

#pragma unroll
        for (int f = 0; f < 3; f++) {
            int ncol = n0 + nb3 + f * 8 + 2 * tig;
            int ur = u0 + mf * 16 + g;
            *(float2*)&g_ghp[(size_t)(kc * UU_ + ur) * H3_ + ncol] =
                make_float2(acc[f][0], acc[f][1]);
            *(float2*)&g_ghp[(size_t)(kc * UU_ + ur + 8) * H3_ + ncol] =
                make_float2(acc[f][2], acc[f][3]);
        }

        grid_barrier(target);

#pragma unroll
        for (int e = 0; e < 2; e++) {
            int idx = e * (GRU_BLOCKS * GRU_THREADS) + bz * GRU_THREADS + tid;
            int u = idx >> 9;
            int j = idx & 511;
            const float* p0 = g_ghp + (size_t)u * H3_;
            const float* p1 = g_ghp + (size_t)(UU_ + u) * H3_;
            float hr = p0[j]        + p1[j]        + bhh[j];
            float hz = p0[512 + j]  + p1[512 + j]  + bhh[512 + j];
            float hn = p0[1024 + j] + p1[1024 + j] + bhh[1024 + j];
            const float* gi = g_P + (size_t)__ldg(&x[st * UU_ + u]) * H3_;
            float r = 1.f / (1.f + __expf(-(gi[j] + hr)));
            float z = 1.f / (1.f + __expf(-(gi[512 + j] + hz)));
            float a = gi[1024 + j] + r * hn;
            float e2 = __expf(2.f * a);
            float n = 1.f - 2.f / (e2 + 1.f);
            float hprev = hp[(size_t)u * HH_ + j];
            g_out[(size_t)st * UU_ * HH_ + idx] = (1.f - z) * n + z * hprev;
        }

        grid_barrier(target);
    }
}

// ---------------- causal spatiotemporal weight matrix (fp16 out) -------------
__global__ void wmat_kernel()
{
    const int i = blockIdx.x;
    const int u = blockIdx.y;
    const float ti  = g_tT[u * SS_ + i];
    const float sxi = g_sx[u * SS_ + i];
    const float syi = g_sy[u * SS_ + i];

    float lsum = 0.f;
    for (int j = threadIdx.x; j < SS_; j += 256) {
        float wv = 0.f;
        if (j <= i) {
            float dt = ti - g_tT[u * SS_ + j];
            float dx = sxi - g_sx[u * SS_ + j];
            float dy = syi - g_sy[u * SS_ + j];
            float ds = sqrtf(dx * dx + dy * dy);
            wv = __expf(-dt * (F_LT / F_DAY) - F_LS * ds) + 1e-10f;
        }
        g_w_h[((size_t)u * SS_ + i) * SS_ + j] = __float2half_rn(wv);
        lsum += wv;
    }
    __shared__ float red[256];
    red[threadIdx.x] = lsum;
    __syncthreads();
    for (int o = 128; o > 0; o >>= 1) {
        if (threadIdx.x < o) red[threadIdx.x] += red[threadIdx.x + o];
        __syncthreads();
    }
    if (threadIdx.x == 0) g_sumw[u * SS_ + i] = red[0];
}

// copy h_last = out[S-1] to tail of d_out
__global__ void hlast_kernel(float* __restrict__ out)
{
    int i = blockIdx.x * blockDim.x + threadIdx.x;
    if (i < UU_ * HH_)
        out[(size_t)SS_ * UU_ * VV_ + i] = g_out[(size_t)(SS_ - 1) * UU_ * HH_ + i];
}

// ---------------- launcher ---------------------------------------------------
extern "C" void kernel_launch(void* const* d_in, const int* in_sizes, int n_in,
                              void* d_out, int out_size)
{
    const int*   x   = (const int*)d_in[0];
    const float* t   = (const float*)d_in[1];
    const float* s   = (const float*)d_in[2];
    // d_in[3] y_t, d_in[4] y_s, d_in[6] active_user: unused by reference
    const float* h0  = (const float*)d_in[5];
    const float* emb = (const float*)d_in[7];
    const float* Wih = (const float*)d_in[8];
    const float* Whh = (const float*)d_in[9];
    const float* bih = (const float*)d_in[10];
    const float* bhh = (const float*)d_in[11];
    const float* fcw = (const float*)d_in[12];
    const float* fcb = (const float*)d_in[13];
    float* out = (float*)d_out;

    static const int GRU_SMEM = (2 * 96 * KSTR + 2 * 32 * KSTR) * 2;   // 135168 B
    cudaFuncSetAttribute(gru_persistent,
                         cudaFuncAttributeMaxDynamicSharedMemorySize, GRU_SMEM);

    // 1. WihT transpose + Whh fp16 hi/lo + fcw fp16 + t/s + barrier reset
    prep_kernel<<<(VV_ * HH_ + 255) / 256, 256>>>(Wih, Whh, fcw, t, s);

    // 2. P = emb @ Wih^T + bih  (2048x1536x512 — replaces entire gi GEMM)
    pgemm<<<dim3(H3_ / 128, VV_ / 128), 256>>>(emb, bih);

    // 3. GRU recurrence (phase A = fp16 mma 3-pass; gi gathered from P)
    gru_persistent<<<GRU_BLOCKS, GRU_THREADS, GRU_SMEM>>>(h0, bhh, x);

    // 4. causal spatiotemporal weights (fp16) + row sums
    wmat_kernel<<<dim3(SS_, UU_), 256>>>();

    // 5a. transpose out -> fp16 [U][H][S]
    outT_kernel<<<dim3(SS_ / 32, HH_ / 32, UU_), dim3(32, 8)>>>();

    // 5b. out_w = (w @ out) / sum_w  (fp16 mma, triangular K) -> fp16 outw
    attn_gemm_h<<<dim3(HH_ / 128, SS_ / 128, UU_), 256>>>();

    // 6. y = out_w @ fc_w^T + fc_b  (fp16 1-pass mma.sync)
    tgemm_fc<<<dim3(VV_ / 128, (SS_ * UU_) / 128), 256>>>(fcb, out);

    // 7. h_last
    hlast_kernel<<<(UU_ * HH_ + 255) / 256, 256>>>(out);
}

// round 17
// speedup vs baseline: 2.3649x; 1.0093x over previous
#include <cuda_runtime.h>
#include <cuda_bf16.h>
#include <cuda_fp16.h>
#include <math.h>
#include <stdint.h>

// Problem constants
#define SS_ 512   // sequence
#define UU_ 128   // users (batch)
#define HH_ 512   // hidden
#define H3_ 1536  // 3*H
#define VV_ 2048  // vocab
#define F_DAY 86400.0f
#define F_LT  0.1f
#define F_LS  1.0f

#define GRU_BLOCKS 128
#define GRU_THREADS 256
#define KSTR 264   // GRU smem k-stride in fp16 (conflict-free frag loads)

typedef unsigned long long u64t;

// ---------------- packed fp32x2 helpers (Blackwell FFMA2) --------------------
__device__ __forceinline__ u64t pk2(float lo, float hi) {
    u64t r; asm("mov.b64 %0, {%1, %2};" : "=l"(r) : "f"(lo), "f"(hi)); return r;
}
__device__ __forceinline__ void ffma2(u64t& d, u64t a, u64t b) {
    asm("fma.rn.f32x2 %0, %1, %2, %0;" : "+l"(d) : "l"(a), "l"(b));
}
__device__ __forceinline__ float2 upk(u64t v) {
    float2 r; asm("mov.b64 {%0, %1}, %2;" : "=f"(r.x), "=f"(r.y) : "l"(v)); return r;
}

// ---------------- fp16 mma.sync helpers (standard PTX, works on sm_103) ------
__device__ __forceinline__ void mma_hf(float* d, const uint32_t* a, uint32_t b0, uint32_t b1) {
    asm volatile(
        "mma.sync.aligned.m16n8k16.row.col.f32.f16.f16.f32 "
        "{%0,%1,%2,%3}, {%4,%5,%6,%7}, {%8,%9}, {%0,%1,%2,%3};"
        : "+f"(d[0]), "+f"(d[1]), "+f"(d[2]), "+f"(d[3])
        : "r"(a[0]), "r"(a[1]), "r"(a[2]), "r"(a[3]), "r"(b0), "r"(b1));
}
// pack float4 -> 4 fp16 (uint2)
__device__ __forceinline__ uint2 cvt4h(float4 v) {
    __half2 p0 = __floats2half2_rn(v.x, v.y);
    __half2 p1 = __floats2half2_rn(v.z, v.w);
    uint2 r;
    r.x = *reinterpret_cast<uint32_t*>(&p0);
    r.y = *reinterpret_cast<uint32_t*>(&p1);
    return r;
}
// split float4 into fp16 hi + fp16 residual lo (each packed uint2)
__device__ __forceinline__ void cvt4hl(float4 v, uint2& h, uint2& l) {
    __half2 h01 = __floats2half2_rn(v.x, v.y);
    __half2 h23 = __floats2half2_rn(v.z, v.w);
    h.x = *reinterpret_cast<uint32_t*>(&h01);
    h.y = *reinterpret_cast<uint32_t*>(&h23);
    __half2 l01 = __floats2half2_rn(v.x - __low2float(h01), v.y - __high2float(h01));
    __half2 l23 = __floats2half2_rn(v.z - __low2float(h23), v.w - __high2float(h23));
    l.x = *reinterpret_cast<uint32_t*>(&l01);
    l.y = *reinterpret_cast<uint32_t*>(&l23);
}

// ---------------- scratch (device globals; allocation is banned) -------------
__device__ float g_P[(size_t)VV_ * H3_];          // P = emb @ Wih^T + bih  (12.6MB, L2)
__device__ float g_out[(size_t)SS_ * UU_ * HH_];  // [S][U][H]  GRU outputs
__device__ __half g_outT_h[(size_t)UU_ * HH_ * SS_];  // out transposed fp16 [U][H][S]
__device__ __half g_outw_h[(size_t)SS_ * UU_ * HH_];  // outw (fp16)
__device__ __half g_w_h[(size_t)UU_ * SS_ * SS_]; // [U][S][S]  causal weights (fp16)
__device__ float g_sumw[UU_ * SS_];               // [U][S]
__device__ float g_WihT[HH_ * H3_];               // [K=H][N=3H] for P gemm
__device__ __half g_whh_h[(size_t)H3_ * HH_];     // W_hh fp16 hi (original [3H][H])
__device__ __half g_whh_l[(size_t)H3_ * HH_];     // W_hh fp16 lo residual
__device__ __half g_fcw_h[(size_t)VV_ * HH_];     // fc_w fp16
__device__ float g_tT[UU_ * SS_];                 // t transposed [U][S]
__device__ float g_sx[UU_ * SS_];
__device__ float g_sy[UU_ * SS_];
__device__ float g_ghp[2 * UU_ * H3_];            // split-K partials of gh
__device__ unsigned g_cnt;                        // global barrier counter

// ---------------- prep: WihT transpose + Whh/fcw fp16 + t/s + barrier reset --
__global__ void prep_kernel(const float* __restrict__ Wih,
                            const float* __restrict__ Whh,
                            const float* __restrict__ fcw,
                            const float* __restrict__ t,
                            const float* __restrict__ s)
{
    int idx = blockIdx.x * blockDim.x + threadIdx.x;
    if (idx == 0) g_cnt = 0;                      // reset software barrier each replay
    if (idx < HH_ * H3_) {
        int k = idx / H3_, n = idx % H3_;
        g_WihT[idx] = Wih[(size_t)n * HH_ + k];
        float f = Whh[idx];
        __half h = __float2half_rn(f);
        g_whh_h[idx] = h;
        g_whh_l[idx] = __float2half_rn(f - __half2float(h));
    }
    if (idx < VV_ * HH_) {
        g_fcw_h[idx] = __float2half_rn(fcw[idx]);
    }
    if (idx < UU_ * SS_) {
        int u = idx / SS_, i = idx % SS_;
        g_tT[idx] = t[(size_t)i * UU_ + u];
        g_sx[idx] = s[((size_t)i * UU_ + u) * 2 + 0];
        g_sy[idx] = s[((size_t)i * UU_ + u) * 2 + 1];
    }
}

// ---------------- P GEMM: P = emb @ Wih^T + bih (FFMA2 128x128x16) -----------
__global__ __launch_bounds__(256, 2)
void pgemm(const float* __restrict__ emb, const float* __restrict__ bih)
{
    const int n0 = blockIdx.x * 128;
    const int m0 = blockIdx.y * 128;
    const float* A = emb;     const int lda = HH_;
    const float* B = g_WihT;  const int ldb = H3_;
    float*       C = g_P;     const int ldc = H3_;

    __shared__ float As[2][16][128];
    __shared__ float Bs[2][16][128];

    const int tid = threadIdx.x;
    const int tx4 = (tid & 15) * 4;
    const int ty4 = (tid >> 4) * 4;

    const int ar  = tid >> 1;
    const int akk = (tid & 1) * 8;
    const float* aRow = A + (size_t)(m0 + ar) * lda + akk;
    const int br  = tid >> 4;
    const int bcc = (tid & 15) * 8;
    const float* bPtr = B + (size_t)br * ldb + n0 + bcc;

    u64t acc[4][8];
#pragma unroll
    for (int i = 0; i < 4; i++)
#pragma unroll
        for (int j = 0; j < 8; j++) acc[i][j] = 0ULL;

    float4 pa0 = *(const float4*)(aRow);
    float4 pa1 = *(const float4*)(aRow + 4);
    float4 pb0 = *(const float4*)(bPtr);
    float4 pb1 = *(const float4*)(bPtr + 4);
    As[0][akk + 0][ar] = pa0.x; As[0][akk + 1][ar] = pa0.y;
    As[0][akk + 2][ar] = pa0.z; As[0][akk + 3][ar] = pa0.w;
    As[0][akk + 4][ar] = pa1.x; As[0][akk + 5][ar] = pa1.y;
    As[0][akk + 6][ar] = pa1.z; As[0][akk + 7][ar] = pa1.w;
    *(float4*)&Bs[0][br][bcc]     = pb0;
    *(float4*)&Bs[0][br][bcc + 4] = pb1;
    __syncthreads();

    const int nk = HH_ >> 4;
    int buf = 0;
    for (int kt = 0; kt < nk; kt++) {
        if (kt + 1 < nk) {
            int kn = (kt + 1) << 4;
            pa0 = *(const float4*)(aRow + kn);
            pa1 = *(const float4*)(aRow + kn + 4);
            pb0 = *(const float4*)(bPtr + (size_t)kn * ldb);
            pb1 = *(const float4*)(bPtr + (size_t)kn * ldb + 4);
        }
#pragma unroll
        for (int k = 0; k < 16; k++) {
            float4 a0 = *(const float4*)&As[buf][k][ty4];
            float4 a1 = *(const float4*)&As[buf][k][64 + ty4];
            float4 b0 = *(const float4*)&Bs[buf][k][tx4];
            float4 b1 = *(const float4*)&Bs[buf][k][64 + tx4];
            u64t ap[4];
            ap[0] = pk2(a0.x, a0.y); ap[1] = pk2(a0.z, a0.w);
            ap[2] = pk2(a1.x, a1.y); ap[3] = pk2(a1.z, a1.w);
            u64t bd[8];
            bd[0] = pk2(b0.x, b0.x); bd[1] = pk2(b0.y, b0.y);
            bd[2] = pk2(b0.z, b0.z); bd[3] = pk2(b0.w, b0.w);
            bd[4] = pk2(b1.x, b1.x); bd[5] = pk2(b1.y, b1.y);
            bd[6] = pk2(b1.z, b1.z); bd[7] = pk2(b1.w, b1.w);
#pragma unroll
            for (int i = 0; i < 4; i++)
#pragma unroll
                for (int j = 0; j < 8; j++)
                    ffma2(acc[i][j], ap[i], bd[j]);
        }
        if (kt + 1 < nk) {
            int nb = buf ^ 1;
            As[nb][akk + 0][ar] = pa0.x; As[nb][akk + 1][ar] = pa0.y;
            As[nb][akk + 2][ar] = pa0.z; As[nb][akk + 3][ar] = pa0.w;
            As[nb][akk + 4][ar] = pa1.x; As[nb][akk + 5][ar] = pa1.y;
            As[nb][akk + 6][ar] = pa1.z; As[nb][akk + 7][ar] = pa1.w;
            *(float4*)&Bs[nb][br][bcc]     = pb0;
            *(float4*)&Bs[nb][br][bcc + 4] = pb1;
            __syncthreads();
            buf = nb;
        }
    }

    float bv[8];
#pragma unroll
    for (int j = 0; j < 8; j++)
        bv[j] = bih[n0 + ((j < 4) ? (tx4 + j) : (64 + tx4 + j - 4))];
#pragma unroll
    for (int mp = 0; mp < 4; mp++) {
        int r = m0 + ((mp >= 2) ? 64 : 0) + ty4 + (mp & 1) * 2;
        float2 v[8];
#pragma unroll
        for (int j = 0; j < 8; j++) v[j] = upk(acc[mp][j]);
        float4 lo0 = make_float4(v[0].x + bv[0], v[1].x + bv[1], v[2].x + bv[2], v[3].x + bv[3]);
        float4 lo1 = make_float4(v[4].x + bv[4], v[5].x + bv[5], v[6].x + bv[6], v[7].x + bv[7]);
        float4 hi0 = make_float4(v[0].y + bv[0], v[1].y + bv[1], v[2].y + bv[2], v[3].y + bv[3]);
        float4 hi1 = make_float4(v[4].y + bv[4], v[5].y + bv[5], v[6].y + bv[6], v[7].y + bv[7]);
        float* c0 = C + (size_t)r * ldc + n0;
        float* c1 = C + (size_t)(r + 1) * ldc + n0;
        *(float4*)&c0[tx4]      = lo0;
        *(float4*)&c0[64 + tx4] = lo1;
        *(float4*)&c1[tx4]      = hi0;
        *(float4*)&c1[64 + tx4] = hi1;
    }
}

// ---------------- fc GEMM: fp16 1-pass mma.sync, double-buffered -------------
#define TSTR 40   // smem row stride in fp16 (conflict-free frag loads)

__global__ __launch_bounds__(256, 2)
void tgemm_fc(const float* __restrict__ bias, float* __restrict__ Cout)
{
    __shared__ uint16_t sA[2][128 * TSTR];
    __shared__ uint16_t sB[2][128 * TSTR];

    const int tid = threadIdx.x;
    const int wid = tid >> 5, lid = tid & 31;
    const int g   = lid >> 2, tig = lid & 3;
    const int wm  = wid & 1;
    const int wn  = wid >> 1;
    const int n0  = blockIdx.x * 128;
    const int m0  = blockIdx.y * 128;

    const int fr = tid >> 1;
    const int kh = (tid & 1) * 16;
    const uint16_t* aS = (const uint16_t*)g_outw_h + (size_t)(m0 + fr) * HH_ + kh;
    const uint16_t* bS = (const uint16_t*)g_fcw_h  + (size_t)(n0 + fr) * HH_ + kh;
    const int soff = fr * TSTR + kh;

    float acc[4][4][4];
#pragma unroll
    for (int i = 0; i < 4; i++)
#pragma unroll
        for (int j = 0; j < 4; j++)
#pragma unroll
            for (int q = 0; q < 4; q++) acc[i][j][q] = 0.f;

    // prologue: chunk 0 -> buffer 0
    {
        const uint4* p;
        uint4* d;
        p = (const uint4*)aS; d = (uint4*)&sA[0][soff]; d[0] = p[0]; d[1] = p[1];
        p = (const uint4*)bS; d = (uint4*)&sB[0][soff]; d[0] = p[0]; d[1] = p[1];
    }
    __syncthreads();

    int buf = 0;
    for (int kb = 0; kb < HH_; kb += 32) {
        uint4 na0, na1, nb0, nb1;
        const bool more = (kb + 32) < HH_;
        if (more) {
            const uint4* p;
            p = (const uint4*)(aS + kb + 32); na0 = p[0]; na1 = p[1];
            p = (const uint4*)(bS + kb + 32); nb0 = p[0]; nb1 = p[1];
        }
#pragma unroll
        for (int k16 = 0; k16 < 32; k16 += 16) {
            uint32_t bh[4][2];
#pragma unroll
            for (int nf = 0; nf < 4; nf++) {
                int nb = (wn * 32 + nf * 8 + g) * TSTR + k16 + 2 * tig;
                bh[nf][0] = *(const uint32_t*)&sB[buf][nb];
                bh[nf][1] = *(const uint32_t*)&sB[buf][nb + 8];
            }
#pragma unroll
            for (int mf = 0; mf < 4; mf++) {
                int ab = (wm * 64 + mf * 16 + g) * TSTR + k16 + 2 * tig;
                uint32_t ah[4];
                ah[0] = *(const uint32_t*)&sA[buf][ab];
                ah[1] = *(const uint32_t*)&sA[buf][ab + 8 * TSTR];
                ah[2] = *(const uint32_t*)&sA[buf][ab + 8];
                ah[3] = *(const uint32_t*)&sA[buf][ab + 8 * TSTR + 8];
#pragma unroll
                for (int nf = 0; nf < 4; nf++)
                    mma_hf(acc[mf][nf], ah, bh[nf][0], bh[nf][1]);
            }
        }
        if (more) {
            uint4* d;
            d = (uint4*)&sA[buf ^ 1][soff]; d[0] = na0; d[1] = na1;
            d = (uint4*)&sB[buf ^ 1][soff]; d[0] = nb0; d[1] = nb1;
            __syncthreads();
            buf ^= 1;
        }
    }

#pragma unroll
    for (int nf = 0; nf < 4; nf++) {
        int col = n0 + wn * 32 + nf * 8 + 2 * tig;
        float2 bb = *(const float2*)&bias[col];
#pragma unroll
        for (int mf = 0; mf < 4; mf++) {
            int row = m0 + wm * 64 + mf * 16 + g;
            float2 v0 = make_float2(acc[mf][nf][0] + bb.x, acc[mf][nf][1] + bb.y);
            float2 v1 = make_float2(acc[mf][nf][2] + bb.x, acc[mf][nf][3] + bb.y);
            *(float2*)&Cout[(size_t)row * VV_ + col]       = v0;
            *(float2*)&Cout[(size_t)(row + 8) * VV_ + col] = v1;
        }
    }
}

// ---------------- out transpose: g_out [S][U][H] f32 -> g_outT [U][H][S] fp16 -
__global__ void outT_kernel()
{
    __shared__ __half tile[32][33];
    const int j0 = blockIdx.x * 32;
    const int h0 = blockIdx.y * 32;
    const int u  = blockIdx.z;
    const int tx = threadIdx.x, ty = threadIdx.y;   // 32 x 8
#pragma unroll
    for (int q = 0; q < 4; q++) {
        int j = j0 + ty + q * 8;
        tile[ty + q * 8][tx] =
            __float2half_rn(g_out[((size_t)j * UU_ + u) * HH_ + h0 + tx]);
    }
    __syncthreads();
#pragma unroll
    for (int q = 0; q < 4; q++) {
        int h = h0 + ty + q * 8;
        g_outT_h[((size_t)u * HH_ + h) * SS_ + j0 + tx] = tile[tx][ty + q * 8];
    }
}

// ---------------- attention GEMM: fp16 mma, double-buffered, triangular K ----
__global__ __launch_bounds__(256, 2)
void attn_gemm_h()
{
    __shared__ uint16_t sA[2][128 * TSTR];
    __shared__ uint16_t sB[2][128 * TSTR];

    const int tid = threadIdx.x;
    const int wid = tid >> 5, lid = tid & 31;
    const int g   = lid >> 2, tig = lid & 3;
    const int wm  = wid & 1;
    const int wn  = wid >> 1;
    const int n0  = blockIdx.x * 128;   // h
    const int m0  = blockIdx.y * 128;   // i
    const int u   = blockIdx.z;
    const int kmax = m0 + 128;          // triangular K limit

    const int fr = tid >> 1;
    const int kh = (tid & 1) * 16;
    const uint16_t* aS = (const uint16_t*)g_w_h    + ((size_t)u * SS_ + m0 + fr) * SS_ + kh;
    const uint16_t* bS = (const uint16_t*)g_outT_h + ((size_t)u * HH_ + n0 + fr) * SS_ + kh;
    const int soff = fr * TSTR + kh;

    float acc[4][4][4];
#pragma unroll
    for (int i = 0; i < 4; i++)
#pragma unroll
        for (int j = 0; j < 4; j++)
#pragma unroll
            for (int q = 0; q < 4; q++) acc[i][j][q] = 0.f;

    {
        const uint4* p;
        uint4* d;
        p = (const uint4*)aS; d = (uint4*)&sA[0][soff]; d[0] = p[0]; d[1] = p[1];
        p = (const uint4*)bS; d = (uint4*)&sB[0][soff]; d[0] = p[0]; d[1] = p[1];
    }
    __syncthreads();

    int buf = 0;
    for (int kb = 0; kb < kmax; kb += 32) {
        uint4 na0, na1, nb0, nb1;
        const bool more = (kb + 32) < kmax;
        if (more) {
            const uint4* p;
            p = (const uint4*)(aS + kb + 32); na0 = p[0]; na1 = p[1];
            p = (const uint4*)(bS + kb + 32); nb0 = p[0]; nb1 = p[1];
        }
#pragma unroll
        for (int k16 = 0; k16 < 32; k16 += 16) {
            uint32_t bh[4][2];
#pragma unroll
            for (int nf = 0; nf < 4; nf++) {
                int nb = (wn * 32 + nf * 8 + g) * TSTR + k16 + 2 * tig;
                bh[nf][0] = *(const uint32_t*)&sB[buf][nb];
                bh[nf][1] = *(const uint32_t*)&sB[buf][nb + 8];
            }
#pragma unroll
            for (int mf = 0; mf < 4; mf++) {
                int ab = (wm * 64 + mf * 16 + g) * TSTR + k16 + 2 * tig;
                uint32_t ah[4];
                ah[0] = *(const uint32_t*)&sA[buf][ab];
                ah[1] = *(const uint32_t*)&sA[buf][ab + 8 * TSTR];
                ah[2] = *(const uint32_t*)&sA[buf][ab + 8];
                ah[3] = *(const uint32_t*)&sA[buf][ab + 8 * TSTR + 8];
#pragma unroll
                for (int nf = 0; nf < 4; nf++)
                    mma_hf(acc[mf][nf], ah, bh[nf][0], bh[nf][1]);
            }
        }
        if (more) {
            uint4* d;
            d = (uint4*)&sA[buf ^ 1][soff]; d[0] = na0; d[1] = na1;
            d = (uint4*)&sB[buf ^ 1][soff]; d[0] = nb0; d[1] = nb1;
            __syncthreads();
            buf ^= 1;
        }
    }

    // epilogue: scale by 1/sumw, write fp16 outw [S][U][H]
#pragma unroll
    for (int mf = 0; mf < 4; mf++) {
        int row0 = m0 + wm * 64 + mf * 16 + g;
        float s0 = 1.f / g_sumw[u * SS_ + row0];
        float s1 = 1.f / g_sumw[u * SS_ + row0 + 8];
        __half* c0 = g_outw_h + ((size_t)row0 * UU_ + u) * HH_;
        __half* c1 = g_outw_h + ((size_t)(row0 + 8) * UU_ + u) * HH_;
#pragma unroll
        for (int nf = 0; nf < 4; nf++) {
            int col = n0 + wn * 32 + nf * 8 + 2 * tig;
            __half2 v0 = __floats2half2_rn(acc[mf][nf][0] * s0, acc[mf][nf][1] * s0);
            __half2 v1 = __floats2half2_rn(acc[mf][nf][2] * s1, acc[mf][nf][3] * s1);
            *(__half2*)&c0[col] = v0;
            *(__half2*)&c1[col] = v1;
        }
    }
}

// ---------------- persistent GRU: all 512 steps in ONE kernel ----------------
__device__ __forceinline__ void grid_barrier(unsigned& target)
{
    __syncthreads();
    if (threadIdx.x == 0) {
        __threadfence();
        atomicAdd(&g_cnt, 1u);
        target += GRU_BLOCKS;
        while (*(volatile unsigned*)&g_cnt < target) { }
        __threadfence();
    }
    __syncthreads();
}

__global__ __launch_bounds__(GRU_THREADS)
void gru_persistent(const float* __restrict__ h0,
                    const float* __restrict__ bhh,
                    const int* __restrict__ x)
{
    extern __shared__ uint16_t hsm[];
    uint16_t* WH = hsm;                      // [96][KSTR] W_hh hi
    uint16_t* WL = hsm + 96 * KSTR;          // [96][KSTR] W_hh lo
    uint16_t* HHs = hsm + 2 * 96 * KSTR;     // [32][KSTR] h hi
    uint16_t* HLs = HHs + 32 * KSTR;         // [32][KSTR] h lo

    const int bz = blockIdx.x;
    const int kc = bz & 1;
    const int u0 = ((bz >> 1) & 3) * 32;
    const int n0 = (bz >> 3) * 96;
    const int kbase = kc * 256;

    const int tid = threadIdx.x;
    const int w   = tid >> 5, lid = tid & 31;
    const int g   = lid >> 2, tig = lid & 3;
    const int mf  = w & 1;
    const int nb3 = (w >> 1) * 24;

    for (int fi = tid; fi < 96 * 32; fi += GRU_THREADS) {
        int n = fi >> 5;
        int k8 = (fi & 31) * 8;
        const __half* sh = g_whh_h + (size_t)(n0 + n) * HH_ + kbase + k8;
        const __half* sl = g_whh_l + (size_t)(n0 + n) * HH_ + kbase + k8;
        *(uint4*)&WH[n * KSTR + k8] = *(const uint4*)sh;
        *(uint4*)&WL[n * KSTR + k8] = *(const uint4*)sl;
    }

    const int fu = tid >> 3;
    const int fj = (tid & 7) * 4;

    unsigned target = 0;

    for (int st = 0; st < SS_; st++) {
        const float* hp = (st == 0) ? h0 : (g_out + (size_t)(st - 1) * UU_ * HH_);

        {
            const float* hrow = hp + (size_t)(u0 + fu) * HH_ + kbase;
            uint16_t* dH = &HHs[fu * KSTR];
            uint16_t* dL = &HLs[fu * KSTR];
#pragma unroll
            for (int i = 0; i < 8; i++) {
                int k4 = fj + 32 * i;
                float4 v = *(const float4*)&hrow[k4];
                uint2 hh, ll;
                cvt4hl(v, hh, ll);
                *(uint2*)&dH[k4] = hh;
                *(uint2*)&dL[k4] = ll;
            }
        }
        __syncthreads();

        float acc[3][4];
#pragma unroll
        for (int f = 0; f < 3; f++)
#pragma unroll
            for (int q = 0; q < 4; q++) acc[f][q] = 0.f;

#pragma unroll 4
        for (int k16 = 0; k16 < 256; k16 += 16) {
            int ab = (mf * 16 + g) * KSTR + k16 + 2 * tig;
            uint32_t ah[4], al[4];
            ah[0] = *(const uint32_t*)&HHs[ab];
            ah[1] = *(const uint32_t*)&HHs[ab + 8 * KSTR];
            ah[2] = *(const uint32_t*)&HHs[ab + 8];
            ah[3] = *(const uint32_t*)&HHs[ab + 8 * KSTR + 8];
            al[0] = *(const uint32_t*)&HLs[ab];
            al[1] = *(const uint32_t*)&HLs[ab + 8 * KSTR];
            al[2] = *(const uint32_t*)&HLs[ab + 8];
            al[3] = *(const uint32_t*)&HLs[ab + 8 * KSTR + 8];
#pragma unroll
            for (int f = 0; f < 3; f++) {
                int nbr = (nb3 + f * 8 + g) * KSTR + k16 + 2 * tig;
                uint32_t bh0 = *(const uint32_t*)&WH[nbr];
                uint32_t bh1 = *(const uint32_t*)&WH[nbr + 8];
                uint32_t bl0 = *(const uint32_t*)&WL[nbr];
                uint32_t bl1 = *(const uint32_t*)&WL[nbr + 8];
                mma_hf(acc[f], ah, bh0, bh1);   // Ah*Bh
                mma_hf(acc[f], al, bh0, bh1);   // Al*Bh
                mma_hf(acc[f], ah, bl0, bl1);   // Ah*Bl
            }
        }

#pragma unroll
        for (int f = 0; f < 3; f++) {
            int ncol = n0 + nb3 + f * 8 + 2 * tig;
            int ur = u0 + mf * 16 + g;
            *(float2*)&g_ghp[(size_t)(kc * UU_ + ur) * H3_ + ncol] =
                make_float2(acc[f][0], acc[f][1]);
            *(float2*)&g_ghp[(size_t)(kc * UU_ + ur + 8) * H3_ + ncol] =
                make_float2(acc[f][2], acc[f][3]);
        }

        grid_barrier(target);

#pragma unroll
        for (int e = 0; e < 2; e++) {
            int idx = e * (GRU_BLOCKS * GRU_THREADS) + bz * GRU_THREADS + tid;
            int u = idx >> 9;
            int j = idx & 511;
            const float* p0 = g_ghp + (size_t)u * H3_;
            const float* p1 = g_ghp + (size_t)(UU_ + u) * H3_;
            float hr = p0[j]        + p1[j]        + bhh[j];
            float hz = p0[512 + j]  + p1[512 + j]  + bhh[512 + j];
            float hn = p0[1024 + j] + p1[1024 + j] + bhh[1024 + j];
            const float* gi = g_P + (size_t)__ldg(&x[st * UU_ + u]) * H3_;
            float r = 1.f / (1.f + __expf(-(gi[j] + hr)));
            float z = 1.f / (1.f + __expf(-(gi[512 + j] + hz)));
            float a = gi[1024 + j] + r * hn;
            float e2 = __expf(2.f * a);
            float n = 1.f - 2.f / (e2 + 1.f);
            float hprev = hp[(size_t)u * HH_ + j];
            g_out[(size_t)st * UU_ * HH_ + idx] = (1.f - z) * n + z * hprev;
        }

        grid_barrier(target);
    }
}

// ---------------- causal spatiotemporal weight matrix (fp16 out) -------------
__global__ void wmat_kernel()
{
    const int i = blockIdx.x;
    const int u = blockIdx.y;
    const float ti  = g_tT[u * SS_ + i];
    const float sxi = g_sx[u * SS_ + i];
    const float syi = g_sy[u * SS_ + i];

    float lsum = 0.f;
    for (int j = threadIdx.x; j < SS_; j += 256) {
        float wv = 0.f;
        if (j <= i) {
            float dt = ti - g_tT[u * SS_ + j];
            float dx = sxi - g_sx[u * SS_ + j];
            float dy = syi - g_sy[u * SS_ + j];
            float ds = sqrtf(dx * dx + dy * dy);
            wv = __expf(-dt * (F_LT / F_DAY) - F_LS * ds) + 1e-10f;
        }
        g_w_h[((size_t)u * SS_ + i) * SS_ + j] = __float2half_rn(wv);
        lsum += wv;
    }
    __shared__ float red[256];
    red[threadIdx.x] = lsum;
    __syncthreads();
    for (int o = 128; o > 0; o >>= 1) {
        if (threadIdx.x < o) red[threadIdx.x] += red[threadIdx.x + o];
        __syncthreads();
    }
    if (threadIdx.x == 0) g_sumw[u * SS_ + i] = red[0];
}

// copy h_last = out[S-1] to tail of d_out
__global__ void hlast_kernel(float* __restrict__ out)
{
    int i = blockIdx.x * blockDim.x + threadIdx.x;
    if (i < UU_ * HH_)
        out[(size_t)SS_ * UU_ * VV_ + i] = g_out[(size_t)(SS_ - 1) * UU_ * HH_ + i];
}

// ---------------- launcher ---------------------------------------------------
extern "C" void kernel_launch(void* const* d_in, const int* in_sizes, int n_in,
                              void* d_out, int out_size)
{
    const int*   x   = (const int*)d_in[0];
    const float* t   = (const float*)d_in[1];
    const float* s   = (const float*)d_in[2];
    // d_in[3] y_t, d_in[4] y_s, d_in[6] active_user: unused by reference
    const float* h0  = (const float*)d_in[5];
    const float* emb = (const float*)d_in[7];
    const float* Wih = (const float*)d_in[8];
    const float* Whh = (const float*)d_in[9];
    const float* bih = (const float*)d_in[10];
    const float* bhh = (const float*)d_in[11];
    const float* fcw = (const float*)d_in[12];
    const float* fcb = (const float*)d_in[13];
    float* out = (float*)d_out;

    static const int GRU_SMEM = (2 * 96 * KSTR + 2 * 32 * KSTR) * 2;   // 135168 B
    cudaFuncSetAttribute(gru_persistent,
                         cudaFuncAttributeMaxDynamicSharedMemorySize, GRU_SMEM);

    // 1. WihT transpose + Whh fp16 hi/lo + fcw fp16 + t/s + barrier reset
    prep_kernel<<<(VV_ * HH_ + 255) / 256, 256>>>(Wih, Whh, fcw, t, s);

    // 2. P = emb @ Wih^T + bih  (2048x1536x512 — replaces entire gi GEMM)
    pgemm<<<dim3(H3_ / 128, VV_ / 128), 256>>>(emb, bih);

    // 3. GRU recurrence (phase A = fp16 mma 3-pass; gi gathered from P)
    gru_persistent<<<GRU_BLOCKS, GRU_THREADS, GRU_SMEM>>>(h0, bhh, x);

    // 4. causal spatiotemporal weights (fp16) + row sums
    wmat_kernel<<<dim3(SS_, UU_), 256>>>();

    // 5a. transpose out -> fp16 [U][H][S]
    outT_kernel<<<dim3(SS_ / 32, HH_ / 32, UU_), dim3(32, 8)>>>();

    // 5b. out_w = (w @ out) / sum_w  (fp16 mma, double-buffered, triangular K)
    attn_gemm_h<<<dim3(HH_ / 128, SS_ / 128, UU_), 256>>>();

    // 6. y = out_w @ fc_w^T + fc_b  (fp16 mma, double-buffered)
    tgemm_fc<<<dim3(VV_ / 128, (SS_ * UU_) / 128), 256>>>(fcb, out);

    // 7. h_last
    hlast_kernel<<<(UU_ * HH_ + 255) / 256, 256>>>(out);
}